// round 8
// baseline (speedup 1.0000x reference)
#include <cuda_runtime.h>
#include <cuda_bf16.h>
#include <math.h>
#include <stdint.h>

#define BATCH 2
#define SEQ   2048
#define DMOD  1024
#define NH    16
#define DK    64
#define MROWS (BATCH*SEQ)   // 4096

// ------------------------- global scratch (no allocs) -----------------------
__device__ __nv_bfloat16 g_Xh[MROWS*DMOD], g_Xl[MROWS*DMOD];
__device__ __nv_bfloat16 g_Wh[4*DMOD*DMOD], g_Wl[4*DMOD*DMOD];
__device__ __nv_bfloat16 g_Qh[BATCH*NH*SEQ*DK], g_Ql[BATCH*NH*SEQ*DK];
__device__ __nv_bfloat16 g_Kh[BATCH*NH*SEQ*DK], g_Kl[BATCH*NH*SEQ*DK];
__device__ __nv_bfloat16 g_Vh[BATCH*NH*SEQ*DK], g_Vl[BATCH*NH*SEQ*DK];
__device__ __nv_bfloat16 g_Oh[MROWS*DMOD], g_Ol[MROWS*DMOD];
__device__ float2 g_cs[SEQ][DK/2];   // (cos, sin) per (pos, pair)

// ------------------------------- helpers ------------------------------------
__device__ __forceinline__ void split2(float e, float o, uint32_t& hi, uint32_t& lo)
{
    __nv_bfloat16 eh = __float2bfloat16(e);
    __nv_bfloat16 oh = __float2bfloat16(o);
    float er  = e - __bfloat162float(eh);
    float orr = o - __bfloat162float(oh);
    __nv_bfloat16 el = __float2bfloat16(er);
    __nv_bfloat16 ol = __float2bfloat16(orr);
    hi = (uint32_t)__bfloat16_as_ushort(eh) | ((uint32_t)__bfloat16_as_ushort(oh) << 16);
    lo = (uint32_t)__bfloat16_as_ushort(el) | ((uint32_t)__bfloat16_as_ushort(ol) << 16);
}

__device__ __forceinline__ void mma16816(float* c, const uint32_t* a, const uint32_t* b)
{
    asm volatile(
        "mma.sync.aligned.m16n8k16.row.col.f32.bf16.bf16.f32 "
        "{%0,%1,%2,%3}, {%4,%5,%6,%7}, {%8,%9}, {%0,%1,%2,%3};\n"
        : "+f"(c[0]), "+f"(c[1]), "+f"(c[2]), "+f"(c[3])
        : "r"(a[0]), "r"(a[1]), "r"(a[2]), "r"(a[3]), "r"(b[0]), "r"(b[1]));
}

__device__ __forceinline__ void ldsm_x4(uint32_t* r, uint32_t addr)
{
    asm volatile("ldmatrix.sync.aligned.m8n8.x4.shared.b16 {%0,%1,%2,%3}, [%4];"
                 : "=r"(r[0]), "=r"(r[1]), "=r"(r[2]), "=r"(r[3]) : "r"(addr));
}
__device__ __forceinline__ void ldsm_x4_t(uint32_t* r, uint32_t addr)
{
    asm volatile("ldmatrix.sync.aligned.m8n8.x4.trans.shared.b16 {%0,%1,%2,%3}, [%4];"
                 : "=r"(r[0]), "=r"(r[1]), "=r"(r[2]), "=r"(r[3]) : "r"(addr));
}
__device__ __forceinline__ void cpa16(uint32_t dst, const void* src)
{
    asm volatile("cp.async.cg.shared.global [%0], [%1], 16;" :: "r"(dst), "l"(src));
}
template<int N> __device__ __forceinline__ void cp_wait()
{
    asm volatile("cp.async.wait_group %0;" :: "n"(N));
}

// -------------------------- prep kernels ------------------------------------
__global__ void rope_table_kernel()
{
    int idx = blockIdx.x * blockDim.x + threadIdx.x;      // SEQ*32
    int s = idx >> 5, j = idx & 31;
    float invf = powf(10000.0f, -(float)(2 * j) / 64.0f);
    float ang = (float)s * invf;
    float sn, cs;
    sincosf(ang, &sn, &cs);
    g_cs[s][j] = make_float2(cs, sn);
}

__global__ void split_kernel(const float* __restrict__ src, int sel, int n4)
{
    int i = blockIdx.x * blockDim.x + threadIdx.x;
    if (i >= n4) return;
    __nv_bfloat16 *h, *l;
    if (sel == 0) { h = g_Xh; l = g_Xl; }
    else { h = g_Wh + (size_t)(sel - 1) * DMOD * DMOD;
           l = g_Wl + (size_t)(sel - 1) * DMOD * DMOD; }
    float4 v = ((const float4*)src)[i];
    uint32_t h0, l0, h1, l1;
    split2(v.x, v.y, h0, l0);
    split2(v.z, v.w, h1, l1);
    *(uint32_t*)&h[4 * i]     = h0;
    *(uint32_t*)&h[4 * i + 2] = h1;
    *(uint32_t*)&l[4 * i]     = l0;
    *(uint32_t*)&l[4 * i + 2] = l1;
}

// ---------------------------------------------------------------------------
// Tensor-core GEMM (3xBF16 split, pre-split inputs): C = A @ W^T
// BM=128, BN=64, BK=32, 256 threads, 8 warps (4x2), warp tile 32x32.
// mode 0: +RoPE -> Qh/Ql   1: +RoPE -> Kh/Kl   2: -> Vh/Vl   3: A=O -> out fp32
// ---------------------------------------------------------------------------
__global__ __launch_bounds__(256) void gemm_mma_kernel(int widx, int mode,
                                                       float* __restrict__ out)
{
    const __nv_bfloat16* Ah = (mode == 3) ? g_Oh : g_Xh;
    const __nv_bfloat16* Al = (mode == 3) ? g_Ol : g_Xl;
    const __nv_bfloat16* Wh = g_Wh + (size_t)widx * DMOD * DMOD;
    const __nv_bfloat16* Wl = g_Wl + (size_t)widx * DMOD * DMOD;

    __shared__ uint32_t sAh[16][136], sAl[16][136];
    __shared__ uint32_t sBh[16][72],  sBl[16][72];

    const int tid  = threadIdx.x;
    const int warp = tid >> 5, lane = tid & 31;
    const int g = lane >> 2, t = lane & 3;
    const int wr = warp >> 1, wc = warp & 1;
    const int m0 = blockIdx.y * 128;
    const int n0 = blockIdx.x * 64;

    float acc[2][4][4];
#pragma unroll
    for (int mt = 0; mt < 2; mt++)
#pragma unroll
        for (int nt = 0; nt < 4; nt++)
#pragma unroll
            for (int i = 0; i < 4; i++) acc[mt][nt][i] = 0.f;

    // global->reg preload indices
    int arow[2], akq[2];
#pragma unroll
    for (int i = 0; i < 2; i++) {
        int lin = tid + 256 * i;
        arow[i] = lin & 127;
        akq[i]  = lin >> 7;     // 0..3 (uint4 within row)
    }
    const int brow = tid & 63, bkq = tid >> 6;

    uint4 rAh[2], rAl[2], rBh, rBl;
#pragma unroll
    for (int i = 0; i < 2; i++) {
        rAh[i] = *(const uint4*)&Ah[(size_t)(m0 + arow[i]) * DMOD + akq[i] * 8];
        rAl[i] = *(const uint4*)&Al[(size_t)(m0 + arow[i]) * DMOD + akq[i] * 8];
    }
    rBh = *(const uint4*)&Wh[(size_t)(n0 + brow) * DMOD + bkq * 8];
    rBl = *(const uint4*)&Wl[(size_t)(n0 + brow) * DMOD + bkq * 8];

    for (int k0 = 0; k0 < DMOD; k0 += 32) {
        __syncthreads();
#pragma unroll
        for (int i = 0; i < 2; i++) {
            int kp = akq[i] * 4, r = arow[i];
            sAh[kp + 0][r] = rAh[i].x; sAh[kp + 1][r] = rAh[i].y;
            sAh[kp + 2][r] = rAh[i].z; sAh[kp + 3][r] = rAh[i].w;
            sAl[kp + 0][r] = rAl[i].x; sAl[kp + 1][r] = rAl[i].y;
            sAl[kp + 2][r] = rAl[i].z; sAl[kp + 3][r] = rAl[i].w;
        }
        {
            int kp = bkq * 4;
            sBh[kp + 0][brow] = rBh.x; sBh[kp + 1][brow] = rBh.y;
            sBh[kp + 2][brow] = rBh.z; sBh[kp + 3][brow] = rBh.w;
            sBl[kp + 0][brow] = rBl.x; sBl[kp + 1][brow] = rBl.y;
            sBl[kp + 2][brow] = rBl.z; sBl[kp + 3][brow] = rBl.w;
        }
        __syncthreads();

        if (k0 + 32 < DMOD) {
            int kn = k0 + 32;
#pragma unroll
            for (int i = 0; i < 2; i++) {
                rAh[i] = *(const uint4*)&Ah[(size_t)(m0 + arow[i]) * DMOD + kn + akq[i] * 8];
                rAl[i] = *(const uint4*)&Al[(size_t)(m0 + arow[i]) * DMOD + kn + akq[i] * 8];
            }
            rBh = *(const uint4*)&Wh[(size_t)(n0 + brow) * DMOD + kn + bkq * 8];
            rBl = *(const uint4*)&Wl[(size_t)(n0 + brow) * DMOD + kn + bkq * 8];
        }

#pragma unroll
        for (int s = 0; s < 2; s++) {
            const int kr = s * 8 + t;
            uint32_t ah[2][4], al[2][4], bh[4][2], bl[4][2];
#pragma unroll
            for (int mt = 0; mt < 2; mt++) {
                int mc = wr * 32 + mt * 16 + g;
                ah[mt][0] = sAh[kr][mc];     ah[mt][1] = sAh[kr][mc + 8];
                ah[mt][2] = sAh[kr + 4][mc]; ah[mt][3] = sAh[kr + 4][mc + 8];
                al[mt][0] = sAl[kr][mc];     al[mt][1] = sAl[kr][mc + 8];
                al[mt][2] = sAl[kr + 4][mc]; al[mt][3] = sAl[kr + 4][mc + 8];
            }
#pragma unroll
            for (int nt = 0; nt < 4; nt++) {
                int nc = wc * 32 + nt * 8 + g;
                bh[nt][0] = sBh[kr][nc]; bh[nt][1] = sBh[kr + 4][nc];
                bl[nt][0] = sBl[kr][nc]; bl[nt][1] = sBl[kr + 4][nc];
            }
#pragma unroll
            for (int mt = 0; mt < 2; mt++)
#pragma unroll
                for (int nt = 0; nt < 4; nt++) {
                    mma16816(acc[mt][nt], al[mt], bh[nt]);
                    mma16816(acc[mt][nt], ah[mt], bl[nt]);
                    mma16816(acc[mt][nt], ah[mt], bh[nt]);
                }
        }
    }

    // ------------------------------- epilogue -------------------------------
#pragma unroll
    for (int mt = 0; mt < 2; mt++) {
#pragma unroll
        for (int rh = 0; rh < 2; rh++) {
            int m  = m0 + wr * 32 + mt * 16 + g + rh * 8;
            int bb = m >> 11;
            int ss = m & (SEQ - 1);
#pragma unroll
            for (int nt = 0; nt < 4; nt++) {
                float c0 = acc[mt][nt][rh * 2 + 0];
                float c1 = acc[mt][nt][rh * 2 + 1];
                int n = n0 + wc * 32 + nt * 8 + t * 2;
                if (mode == 3) {
                    *(float2*)&out[(size_t)m * DMOD + n] = make_float2(c0, c1);
                } else {
                    int h = n >> 6, i0 = n & 63;
                    size_t idx = (((size_t)(bb * NH + h)) * SEQ + ss) * DK + i0;
                    uint32_t hi, lo;
                    if (mode == 2) {
                        split2(c0, c1, hi, lo);
                        *(uint32_t*)&g_Vh[idx] = hi;
                        *(uint32_t*)&g_Vl[idx] = lo;
                    } else {
                        float2 cssn = g_cs[ss][i0 >> 1];
                        float r0 = c0 * cssn.x - c1 * cssn.y;
                        float r1 = c1 * cssn.x + c0 * cssn.y;
                        split2(r0, r1, hi, lo);
                        if (mode == 0) {
                            *(uint32_t*)&g_Qh[idx] = hi;
                            *(uint32_t*)&g_Ql[idx] = lo;
                        } else {
                            *(uint32_t*)&g_Kh[idx] = hi;
                            *(uint32_t*)&g_Kl[idx] = lo;
                        }
                    }
                }
            }
        }
    }
}

// ---------------------------------------------------------------------------
// MMA flash attention, pre-split bf16 inputs, cp.async double-buffered K/V.
// CTA: 64 queries, 4 warps. grid = (SEQ/64, BATCH*NH), block = 128.
// smem stage: Kh|Kl|Vh|Vl tiles, 64 rows x 64 cols bf16, pitch 72 (144B).
// ---------------------------------------------------------------------------
#define TPITCH 144                    // bytes per smem row
#define TILE_B (64*TPITCH)            // 9216 B per tile
#define STAGE_B (4*TILE_B)            // 36864 B per stage

__global__ __launch_bounds__(128) void attn_mma_kernel()
{
    extern __shared__ char smem[];
    const uint32_t smemB = (uint32_t)__cvta_generic_to_shared(smem);

    const int tid  = threadIdx.x;
    const int w    = tid >> 5;
    const int lane = tid & 31;
    const int g = lane >> 2, t = lane & 3;
    const int qt = (int)gridDim.x - 1 - (int)blockIdx.x;   // heavy blocks first
    const int bh = blockIdx.y;
    const int q0 = qt * 64;

    const size_t hb = (size_t)bh * SEQ * DK;
    const __nv_bfloat16* kv_src[4] = {g_Kh + hb, g_Kl + hb, g_Vh + hb, g_Vl + hb};

    // --- Q fragments (direct bf16-pair loads) ---
    uint32_t qh[4][4], ql[4][4];
    {
        const __nv_bfloat16* qh0 = g_Qh + hb + (size_t)(q0 + w * 16 + g) * DK;
        const __nv_bfloat16* ql0 = g_Ql + hb + (size_t)(q0 + w * 16 + g) * DK;
#pragma unroll
        for (int ks = 0; ks < 4; ks++) {
            int c = ks * 16 + 2 * t;
            qh[ks][0] = *(const uint32_t*)&qh0[c];
            qh[ks][1] = *(const uint32_t*)&qh0[8 * DK + c];
            qh[ks][2] = *(const uint32_t*)&qh0[c + 8];
            qh[ks][3] = *(const uint32_t*)&qh0[8 * DK + c + 8];
            ql[ks][0] = *(const uint32_t*)&ql0[c];
            ql[ks][1] = *(const uint32_t*)&ql0[8 * DK + c];
            ql[ks][2] = *(const uint32_t*)&ql0[c + 8];
            ql[ks][3] = *(const uint32_t*)&ql0[8 * DK + c + 8];
        }
    }

    // per-lane partial offsets for ldmatrix.x4
    const uint32_t kPart = (uint32_t)((lane & 7) * TPITCH + (lane >> 3) * 16);
    const uint32_t vPart = (uint32_t)(((lane & 7) + 8 * ((lane >> 3) & 1)) * TPITCH
                                      + (lane >> 4) * 16);

    auto issue = [&](int kt, int stg) {
        uint32_t base = smemB + stg * STAGE_B;
#pragma unroll
        for (int a = 0; a < 4; a++) {
            const __nv_bfloat16* s = kv_src[a] + (size_t)kt * 64 * DK;
#pragma unroll
            for (int i = 0; i < 4; i++) {
                int c = tid + i * 128;                  // 0..511
                cpa16(base + a * TILE_B + (c >> 3) * TPITCH + (c & 7) * 16,
                      s + (c >> 3) * DK + (c & 7) * 8);
            }
        }
        asm volatile("cp.async.commit_group;\n" ::);
    };

    float oacc[8][4];
#pragma unroll
    for (int nt = 0; nt < 8; nt++)
#pragma unroll
        for (int i = 0; i < 4; i++) oacc[nt][i] = 0.f;
    float mrow[2] = {-1e30f, -1e30f};
    float lrow[2] = {0.f, 0.f};

    issue(0, 0);

    for (int kt = 0; kt <= qt; kt++) {
        const int stg = kt & 1;
        if (kt < qt) { issue(kt + 1, stg ^ 1); cp_wait<1>(); }
        else         { cp_wait<0>(); }
        __syncthreads();

        const uint32_t khB = smemB + stg * STAGE_B;
        const uint32_t klB = khB + TILE_B;
        const uint32_t vhB = khB + 2 * TILE_B;
        const uint32_t vlB = khB + 3 * TILE_B;

        // --- S = Q K^T ---
        float sacc[8][4];
#pragma unroll
        for (int nt = 0; nt < 8; nt++) {
#pragma unroll
            for (int i = 0; i < 4; i++) sacc[nt][i] = 0.f;
#pragma unroll
            for (int ks2 = 0; ks2 < 2; ks2++) {
                uint32_t bh4[4], bl4[4];
                uint32_t off = (uint32_t)(nt * 8 * TPITCH + ks2 * 64) + kPart;
                ldsm_x4(bh4, khB + off);
                ldsm_x4(bl4, klB + off);
                mma16816(sacc[nt], ql[2 * ks2],     bh4 + 0);
                mma16816(sacc[nt], qh[2 * ks2],     bl4 + 0);
                mma16816(sacc[nt], qh[2 * ks2],     bh4 + 0);
                mma16816(sacc[nt], ql[2 * ks2 + 1], bh4 + 2);
                mma16816(sacc[nt], qh[2 * ks2 + 1], bl4 + 2);
                mma16816(sacc[nt], qh[2 * ks2 + 1], bh4 + 2);
            }
        }

#pragma unroll
        for (int nt = 0; nt < 8; nt++)
#pragma unroll
            for (int i = 0; i < 4; i++) sacc[nt][i] *= 0.125f;
        if (kt == qt) {
#pragma unroll
            for (int nt = 0; nt < 8; nt++)
#pragma unroll
                for (int i = 0; i < 4; i++) {
                    int col = nt * 8 + 2 * t + (i & 1);
                    int row = w * 16 + g + 8 * (i >> 1);
                    if (col > row) sacc[nt][i] = -1e30f;
                }
        }

        // --- online softmax ---
#pragma unroll
        for (int r = 0; r < 2; r++) {
            float mx = -1e30f;
#pragma unroll
            for (int nt = 0; nt < 8; nt++) {
                mx = fmaxf(mx, sacc[nt][2 * r]);
                mx = fmaxf(mx, sacc[nt][2 * r + 1]);
            }
            mx = fmaxf(mx, __shfl_xor_sync(0xffffffffu, mx, 1));
            mx = fmaxf(mx, __shfl_xor_sync(0xffffffffu, mx, 2));
            float mnew = fmaxf(mrow[r], mx);
            float corr = __expf(mrow[r] - mnew);
            mrow[r] = mnew;
            float rs = 0.f;
#pragma unroll
            for (int nt = 0; nt < 8; nt++) {
                float p0 = __expf(sacc[nt][2 * r]     - mnew);
                float p1 = __expf(sacc[nt][2 * r + 1] - mnew);
                sacc[nt][2 * r] = p0; sacc[nt][2 * r + 1] = p1;
                rs += p0 + p1;
            }
            rs += __shfl_xor_sync(0xffffffffu, rs, 1);
            rs += __shfl_xor_sync(0xffffffffu, rs, 2);
            lrow[r] = lrow[r] * corr + rs;
#pragma unroll
            for (int nt = 0; nt < 8; nt++) {
                oacc[nt][2 * r]     *= corr;
                oacc[nt][2 * r + 1] *= corr;
            }
        }

        // --- O += P V ---
#pragma unroll
        for (int kc = 0; kc < 4; kc++) {
            uint32_t pah[4], pal[4];
            split2(sacc[2 * kc][0],     sacc[2 * kc][1],     pah[0], pal[0]);
            split2(sacc[2 * kc][2],     sacc[2 * kc][3],     pah[1], pal[1]);
            split2(sacc[2 * kc + 1][0], sacc[2 * kc + 1][1], pah[2], pal[2]);
            split2(sacc[2 * kc + 1][2], sacc[2 * kc + 1][3], pah[3], pal[3]);
#pragma unroll
            for (int nt2 = 0; nt2 < 4; nt2++) {
                uint32_t vh4[4], vl4[4];
                uint32_t off = (uint32_t)(kc * 16 * TPITCH + nt2 * 32) + vPart;
                ldsm_x4_t(vh4, vhB + off);
                ldsm_x4_t(vl4, vlB + off);
                mma16816(oacc[2 * nt2],     pah, vh4 + 0);
                mma16816(oacc[2 * nt2],     pah, vl4 + 0);
                mma16816(oacc[2 * nt2],     pal, vh4 + 0);
                mma16816(oacc[2 * nt2 + 1], pah, vh4 + 2);
                mma16816(oacc[2 * nt2 + 1], pah, vl4 + 2);
                mma16816(oacc[2 * nt2 + 1], pal, vh4 + 2);
            }
        }
        __syncthreads();
    }

    // --- epilogue: write split O ---
    const int bb = bh >> 4;
    const int h  = bh & 15;
#pragma unroll
    for (int r = 0; r < 2; r++) {
        float inv = 1.f / lrow[r];
        int q = q0 + w * 16 + g + 8 * r;
        size_t rowoff = ((size_t)(bb * SEQ + q)) * DMOD + h * DK;
#pragma unroll
        for (int nt = 0; nt < 8; nt++) {
            uint32_t hi, lo;
            split2(oacc[nt][2 * r] * inv, oacc[nt][2 * r + 1] * inv, hi, lo);
            *(uint32_t*)&g_Oh[rowoff + nt * 8 + 2 * t] = hi;
            *(uint32_t*)&g_Ol[rowoff + nt * 8 + 2 * t] = lo;
        }
    }
}

// ---------------------------------------------------------------------------
extern "C" void kernel_launch(void* const* d_in, const int* in_sizes, int n_in,
                              void* d_out, int out_size)
{
    const float* X  = (const float*)d_in[0];
    const float* Wq = (const float*)d_in[1];
    const float* Wk = (const float*)d_in[2];
    const float* Wv = (const float*)d_in[3];
    const float* Wo = (const float*)d_in[4];
    float* out = (float*)d_out;

    rope_table_kernel<<<SEQ * 32 / 256, 256>>>();
    split_kernel<<<MROWS * DMOD / 4 / 256, 256>>>(X,  0, MROWS * DMOD / 4);
    split_kernel<<<DMOD * DMOD / 4 / 256, 256>>>(Wq, 1, DMOD * DMOD / 4);
    split_kernel<<<DMOD * DMOD / 4 / 256, 256>>>(Wk, 2, DMOD * DMOD / 4);
    split_kernel<<<DMOD * DMOD / 4 / 256, 256>>>(Wv, 3, DMOD * DMOD / 4);
    split_kernel<<<DMOD * DMOD / 4 / 256, 256>>>(Wo, 4, DMOD * DMOD / 4);

    dim3 ggrid(DMOD / 64, MROWS / 128);   // (16, 32)
    gemm_mma_kernel<<<ggrid, 256>>>(0, 0, nullptr);
    gemm_mma_kernel<<<ggrid, 256>>>(1, 1, nullptr);
    gemm_mma_kernel<<<ggrid, 256>>>(2, 2, nullptr);

    cudaFuncSetAttribute(attn_mma_kernel,
                         cudaFuncAttributeMaxDynamicSharedMemorySize, 2 * STAGE_B);
    attn_mma_kernel<<<dim3(SEQ / 64, BATCH * NH), 128, 2 * STAGE_B>>>();

    gemm_mma_kernel<<<ggrid, 256>>>(3, 3, out);
}

// round 9
// speedup vs baseline: 1.2294x; 1.2294x over previous
#include <cuda_runtime.h>
#include <cuda_bf16.h>
#include <math.h>
#include <stdint.h>

// Problem constants
#define BATCH 2
#define SEQ   2048
#define DMOD  1024
#define NH    16
#define DK    64
#define MROWS (BATCH*SEQ)   // 4096

// Scratch (allocation-free per harness rules)
__device__ float g_Q[BATCH*NH*SEQ*DK];   // [b][h][s][dk], post-RoPE
__device__ float g_K[BATCH*NH*SEQ*DK];   // [b][h][s][dk], post-RoPE
__device__ float g_V[BATCH*NH*SEQ*DK];   // [b][h][s][dk]
__device__ float g_O[MROWS*DMOD];        // [b][s][h*dk]
__device__ float2 g_cs[SEQ][DK/2];       // (cos, sin) per (pos, pair)

// ---------------------------------------------------------------------------
// helpers
// ---------------------------------------------------------------------------
__device__ __forceinline__ void split2(float e, float o, uint32_t& hi, uint32_t& lo)
{
    __nv_bfloat16 eh = __float2bfloat16(e);
    __nv_bfloat16 oh = __float2bfloat16(o);
    float er  = e - __bfloat162float(eh);
    float orr = o - __bfloat162float(oh);
    __nv_bfloat16 el = __float2bfloat16(er);
    __nv_bfloat16 ol = __float2bfloat16(orr);
    hi = (uint32_t)__bfloat16_as_ushort(eh) | ((uint32_t)__bfloat16_as_ushort(oh) << 16);
    lo = (uint32_t)__bfloat16_as_ushort(el) | ((uint32_t)__bfloat16_as_ushort(ol) << 16);
}

__device__ __forceinline__ void mma16816(float* c, const uint32_t* a, const uint32_t* b)
{
    asm volatile(
        "mma.sync.aligned.m16n8k16.row.col.f32.bf16.bf16.f32 "
        "{%0,%1,%2,%3}, {%4,%5,%6,%7}, {%8,%9}, {%0,%1,%2,%3};\n"
        : "+f"(c[0]), "+f"(c[1]), "+f"(c[2]), "+f"(c[3])
        : "r"(a[0]), "r"(a[1]), "r"(a[2]), "r"(a[3]), "r"(b[0]), "r"(b[1]));
}

__device__ __forceinline__ void ldsm_x2(uint32_t& r0, uint32_t& r1, uint32_t addr)
{
    asm volatile("ldmatrix.sync.aligned.m8n8.x2.shared.b16 {%0,%1}, [%2];"
                 : "=r"(r0), "=r"(r1) : "r"(addr));
}
__device__ __forceinline__ void ldsm_x2_t(uint32_t& r0, uint32_t& r1, uint32_t addr)
{
    asm volatile("ldmatrix.sync.aligned.m8n8.x2.trans.shared.b16 {%0,%1}, [%2];"
                 : "=r"(r0), "=r"(r1) : "r"(addr));
}

__device__ __forceinline__ void load_split(const float* p, uint32_t* h, uint32_t* l)
{
    float4 v = *(const float4*)p;
    split2(v.x, v.y, h[0], l[0]);
    split2(v.z, v.w, h[1], l[1]);
}

// -------------------------- prep kernel -------------------------------------
__global__ void rope_table_kernel()
{
    int idx = blockIdx.x * blockDim.x + threadIdx.x;      // SEQ*32
    int s = idx >> 5, j = idx & 31;
    float invf = powf(10000.0f, -(float)(2 * j) / 64.0f);
    float ang = (float)s * invf;
    float sn, cs;
    sincosf(ang, &sn, &cs);
    g_cs[s][j] = make_float2(cs, sn);
}

// ---------------------------------------------------------------------------
// Tensor-core GEMM (3xBF16 split): C = A @ W^T, register-preload pipelined.
// BM=128, BN=64, BK=32, 256 threads, 8 warps (4x2), warp tile 32x32.
// mode_in = -1: fused QKV (mode = blockIdx.x>>4; W from {Wq,Wk,Wv})
// mode_in =  3: A = g_O, W = W0 (=Wo), fp32 out.
// ---------------------------------------------------------------------------
__global__ __launch_bounds__(256) void gemm_mma_kernel(
    const float* __restrict__ Ain,
    const float* __restrict__ W0, const float* __restrict__ W1,
    const float* __restrict__ W2,
    float* __restrict__ out, int mode_in)
{
    int mode, n0;
    const float* W;
    if (mode_in < 0) {
        mode = (int)blockIdx.x >> 4;
        W = (mode == 0) ? W0 : (mode == 1) ? W1 : W2;
        n0 = ((int)blockIdx.x & 15) * 64;
    } else {
        mode = mode_in;
        W = W0;
        n0 = (int)blockIdx.x * 64;
    }
    const float* A = (mode == 3) ? g_O : Ain;

    __shared__ uint32_t sAh[16][136], sAl[16][136];
    __shared__ uint32_t sBh[16][72],  sBl[16][72];

    const int tid  = threadIdx.x;
    const int warp = tid >> 5, lane = tid & 31;
    const int g = lane >> 2, t = lane & 3;
    const int wr = warp >> 1, wc = warp & 1;
    const int m0 = blockIdx.y * 128;

    float acc[2][4][4];
#pragma unroll
    for (int mt = 0; mt < 2; mt++)
#pragma unroll
        for (int nt = 0; nt < 4; nt++)
#pragma unroll
            for (int i = 0; i < 4; i++) acc[mt][nt][i] = 0.f;

    // preload index mapping (same as smem layout mapping)
    int arow[4], akq[4];
#pragma unroll
    for (int i = 0; i < 4; i++) {
        int lin = tid + i * 256;            // 0..1023
        arow[i] = lin >> 3;                 // 0..127
        akq[i]  = (lin & 7) * 4;            // 0,4,...,28
    }
    int brow[2], bkq[2];
#pragma unroll
    for (int i = 0; i < 2; i++) {
        int lin = tid + i * 256;            // 0..511
        brow[i] = lin >> 3;                 // 0..63
        bkq[i]  = (lin & 7) * 4;
    }

    // split tile held in registers (hi/lo packed pairs)
    uint32_t pAh[4][2], pAl[4][2], pBh[2][2], pBl[2][2];
#pragma unroll
    for (int i = 0; i < 4; i++)
        load_split(&A[(size_t)(m0 + arow[i]) * DMOD + akq[i]], pAh[i], pAl[i]);
#pragma unroll
    for (int i = 0; i < 2; i++)
        load_split(&W[(size_t)(n0 + brow[i]) * DMOD + bkq[i]], pBh[i], pBl[i]);

    for (int k0 = 0; k0 < DMOD; k0 += 32) {
        __syncthreads();                    // previous MMA phase done with smem
#pragma unroll
        for (int i = 0; i < 4; i++) {
            int kp = akq[i] >> 1, r = arow[i];
            sAh[kp][r] = pAh[i][0]; sAh[kp + 1][r] = pAh[i][1];
            sAl[kp][r] = pAl[i][0]; sAl[kp + 1][r] = pAl[i][1];
        }
#pragma unroll
        for (int i = 0; i < 2; i++) {
            int kp = bkq[i] >> 1, r = brow[i];
            sBh[kp][r] = pBh[i][0]; sBh[kp + 1][r] = pBh[i][1];
            sBl[kp][r] = pBl[i][0]; sBl[kp + 1][r] = pBl[i][1];
        }
        __syncthreads();

        // preload + split NEXT tile (overlaps with MMA phase below)
        if (k0 + 32 < DMOD) {
            int kn = k0 + 32;
#pragma unroll
            for (int i = 0; i < 4; i++)
                load_split(&A[(size_t)(m0 + arow[i]) * DMOD + kn + akq[i]],
                           pAh[i], pAl[i]);
#pragma unroll
            for (int i = 0; i < 2; i++)
                load_split(&W[(size_t)(n0 + brow[i]) * DMOD + kn + bkq[i]],
                           pBh[i], pBl[i]);
        }

#pragma unroll
        for (int s = 0; s < 2; s++) {
            const int kr = s * 8 + t;
            uint32_t ah[2][4], al[2][4], bh[4][2], bl[4][2];
#pragma unroll
            for (int mt = 0; mt < 2; mt++) {
                int mc = wr * 32 + mt * 16 + g;
                ah[mt][0] = sAh[kr][mc];     ah[mt][1] = sAh[kr][mc + 8];
                ah[mt][2] = sAh[kr + 4][mc]; ah[mt][3] = sAh[kr + 4][mc + 8];
                al[mt][0] = sAl[kr][mc];     al[mt][1] = sAl[kr][mc + 8];
                al[mt][2] = sAl[kr + 4][mc]; al[mt][3] = sAl[kr + 4][mc + 8];
            }
#pragma unroll
            for (int nt = 0; nt < 4; nt++) {
                int nc = wc * 32 + nt * 8 + g;
                bh[nt][0] = sBh[kr][nc]; bh[nt][1] = sBh[kr + 4][nc];
                bl[nt][0] = sBl[kr][nc]; bl[nt][1] = sBl[kr + 4][nc];
            }
#pragma unroll
            for (int mt = 0; mt < 2; mt++)
#pragma unroll
                for (int nt = 0; nt < 4; nt++) {
                    mma16816(acc[mt][nt], al[mt], bh[nt]);
                    mma16816(acc[mt][nt], ah[mt], bl[nt]);
                    mma16816(acc[mt][nt], ah[mt], bh[nt]);
                }
        }
    }

    // ------------------------------- epilogue -------------------------------
#pragma unroll
    for (int mt = 0; mt < 2; mt++) {
#pragma unroll
        for (int rh = 0; rh < 2; rh++) {
            int m  = m0 + wr * 32 + mt * 16 + g + rh * 8;
            int bb = m >> 11;
            int ss = m & (SEQ - 1);
#pragma unroll
            for (int nt = 0; nt < 4; nt++) {
                float c0 = acc[mt][nt][rh * 2 + 0];
                float c1 = acc[mt][nt][rh * 2 + 1];
                int n = n0 + wc * 32 + nt * 8 + t * 2;
                if (mode == 3) {
                    *(float2*)&out[(size_t)m * DMOD + n] = make_float2(c0, c1);
                } else if (mode == 2) {
                    int h = n >> 6, i0 = n & 63;
                    *(float2*)&g_V[(((size_t)(bb * NH + h)) * SEQ + ss) * DK + i0] =
                        make_float2(c0, c1);
                } else {
                    int h = n >> 6, i0 = n & 63;
                    float2 cssn = g_cs[ss][i0 >> 1];
                    float r0 = c0 * cssn.x - c1 * cssn.y;
                    float r1 = c1 * cssn.x + c0 * cssn.y;
                    float* dst = ((mode == 0) ? g_Q : g_K)
                               + (((size_t)(bb * NH + h)) * SEQ + ss) * DK + i0;
                    *(float2*)dst = make_float2(r0, r1);
                }
            }
        }
    }
}

// ---------------------------------------------------------------------------
// MMA flash attention (3xBF16 split for QK^T and PV), causal.  (R3, known-good)
// CTA: 64 queries, 4 warps (16 q-rows each), 64-key tiles in smem.
// grid = (SEQ/64, BATCH*NH), block = 128
// ---------------------------------------------------------------------------
#define VPITCH 72   // bf16 row pitch for K/V smem tiles (conflict-free ldmatrix)

__global__ __launch_bounds__(128) void attn_mma_kernel()
{
    __shared__ __nv_bfloat16 Ksh[64 * VPITCH];
    __shared__ __nv_bfloat16 Ksl[64 * VPITCH];
    __shared__ __nv_bfloat16 Vsh[64 * VPITCH];
    __shared__ __nv_bfloat16 Vsl[64 * VPITCH];

    const int tid  = threadIdx.x;
    const int w    = tid >> 5;
    const int lane = tid & 31;
    const int g = lane >> 2, t = lane & 3;
    const int qt = (int)gridDim.x - 1 - (int)blockIdx.x;   // heavy blocks first
    const int bh = blockIdx.y;
    const int q0 = qt * 64;

    const float* Qb = g_Q + (size_t)bh * SEQ * DK;
    const float* Kb = g_K + (size_t)bh * SEQ * DK;
    const float* Vb = g_V + (size_t)bh * SEQ * DK;

    // --- Q fragments (rows q0 + w*16 + g, g+8), split hi/lo ---
    uint32_t qh[4][4], ql[4][4];
    {
        const float* Qr0 = Qb + (size_t)(q0 + w * 16 + g) * DK;
        const float* Qr8 = Qr0 + 8 * DK;
#pragma unroll
        for (int ks = 0; ks < 4; ks++) {
            float2 x0 = *(const float2*)&Qr0[ks * 16 + 2 * t];
            float2 x1 = *(const float2*)&Qr8[ks * 16 + 2 * t];
            float2 x2 = *(const float2*)&Qr0[ks * 16 + 8 + 2 * t];
            float2 x3 = *(const float2*)&Qr8[ks * 16 + 8 + 2 * t];
            split2(x0.x, x0.y, qh[ks][0], ql[ks][0]);
            split2(x1.x, x1.y, qh[ks][1], ql[ks][1]);
            split2(x2.x, x2.y, qh[ks][2], ql[ks][2]);
            split2(x3.x, x3.y, qh[ks][3], ql[ks][3]);
        }
    }

    const uint32_t khB = (uint32_t)__cvta_generic_to_shared(Ksh);
    const uint32_t klB = (uint32_t)__cvta_generic_to_shared(Ksl);
    const uint32_t vhB = (uint32_t)__cvta_generic_to_shared(Vsh);
    const uint32_t vlB = (uint32_t)__cvta_generic_to_shared(Vsl);
    const uint32_t kPart = ((lane & 7) * VPITCH + 8 * ((lane >> 3) & 1)) * 2;
    const uint32_t vPart = (((lane & 7) + 8 * ((lane >> 3) & 1)) * VPITCH) * 2;

    float oacc[8][4];
#pragma unroll
    for (int nt = 0; nt < 8; nt++)
#pragma unroll
        for (int i = 0; i < 4; i++) oacc[nt][i] = 0.f;
    float mrow[2] = {-1e30f, -1e30f};
    float lrow[2] = {0.f, 0.f};

    for (int kt = 0; kt <= qt; kt++) {
        __syncthreads();
#pragma unroll
        for (int i = 0; i < 8; i++) {
            int lin = i * 128 + tid;
            int row = lin >> 4;
            int c4  = (lin & 15) * 4;
            const float* src = Kb + (size_t)(kt * 64 + row) * DK + c4;
            float4 v = *(const float4*)src;
            uint32_t h0, l0, h1, l1;
            split2(v.x, v.y, h0, l0);
            split2(v.z, v.w, h1, l1);
            *(uint32_t*)&Ksh[row * VPITCH + c4]     = h0;
            *(uint32_t*)&Ksh[row * VPITCH + c4 + 2] = h1;
            *(uint32_t*)&Ksl[row * VPITCH + c4]     = l0;
            *(uint32_t*)&Ksl[row * VPITCH + c4 + 2] = l1;

            const float* sv = Vb + (size_t)(kt * 64 + row) * DK + c4;
            float4 vv = *(const float4*)sv;
            split2(vv.x, vv.y, h0, l0);
            split2(vv.z, vv.w, h1, l1);
            *(uint32_t*)&Vsh[row * VPITCH + c4]     = h0;
            *(uint32_t*)&Vsh[row * VPITCH + c4 + 2] = h1;
            *(uint32_t*)&Vsl[row * VPITCH + c4]     = l0;
            *(uint32_t*)&Vsl[row * VPITCH + c4 + 2] = l1;
        }
        __syncthreads();

        // --- S = Q K^T ---
        float sacc[8][4];
#pragma unroll
        for (int nt = 0; nt < 8; nt++) {
#pragma unroll
            for (int i = 0; i < 4; i++) sacc[nt][i] = 0.f;
            const uint32_t offBase = (uint32_t)(nt * 8 * VPITCH * 2) + kPart;
#pragma unroll
            for (int ks = 0; ks < 4; ks++) {
                uint32_t bhf[2], blf[2];
                ldsm_x2(bhf[0], bhf[1], khB + offBase + ks * 32);
                ldsm_x2(blf[0], blf[1], klB + offBase + ks * 32);
                mma16816(sacc[nt], ql[ks], bhf);
                mma16816(sacc[nt], qh[ks], blf);
                mma16816(sacc[nt], qh[ks], bhf);
            }
        }

#pragma unroll
        for (int nt = 0; nt < 8; nt++)
#pragma unroll
            for (int i = 0; i < 4; i++) sacc[nt][i] *= 0.125f;
        if (kt == qt) {
#pragma unroll
            for (int nt = 0; nt < 8; nt++)
#pragma unroll
                for (int i = 0; i < 4; i++) {
                    int col = nt * 8 + 2 * t + (i & 1);
                    int row = w * 16 + g + 8 * (i >> 1);
                    if (col > row) sacc[nt][i] = -1e30f;
                }
        }

        // --- online softmax ---
#pragma unroll
        for (int r = 0; r < 2; r++) {
            float mx = -1e30f;
#pragma unroll
            for (int nt = 0; nt < 8; nt++) {
                mx = fmaxf(mx, sacc[nt][2 * r]);
                mx = fmaxf(mx, sacc[nt][2 * r + 1]);
            }
            mx = fmaxf(mx, __shfl_xor_sync(0xffffffffu, mx, 1));
            mx = fmaxf(mx, __shfl_xor_sync(0xffffffffu, mx, 2));
            float mnew = fmaxf(mrow[r], mx);
            float corr = __expf(mrow[r] - mnew);
            mrow[r] = mnew;
            float rs = 0.f;
#pragma unroll
            for (int nt = 0; nt < 8; nt++) {
                float p0 = __expf(sacc[nt][2 * r]     - mnew);
                float p1 = __expf(sacc[nt][2 * r + 1] - mnew);
                sacc[nt][2 * r] = p0; sacc[nt][2 * r + 1] = p1;
                rs += p0 + p1;
            }
            rs += __shfl_xor_sync(0xffffffffu, rs, 1);
            rs += __shfl_xor_sync(0xffffffffu, rs, 2);
            lrow[r] = lrow[r] * corr + rs;
#pragma unroll
            for (int nt = 0; nt < 8; nt++) {
                oacc[nt][2 * r]     *= corr;
                oacc[nt][2 * r + 1] *= corr;
            }
        }

        // --- O += P V ---
#pragma unroll
        for (int kc = 0; kc < 4; kc++) {
            uint32_t pah[4], pal[4];
            split2(sacc[2 * kc][0],     sacc[2 * kc][1],     pah[0], pal[0]);
            split2(sacc[2 * kc][2],     sacc[2 * kc][3],     pah[1], pal[1]);
            split2(sacc[2 * kc + 1][0], sacc[2 * kc + 1][1], pah[2], pal[2]);
            split2(sacc[2 * kc + 1][2], sacc[2 * kc + 1][3], pah[3], pal[3]);
            const uint32_t offBase = (uint32_t)(kc * 16 * VPITCH * 2) + vPart;
#pragma unroll
            for (int nt = 0; nt < 8; nt++) {
                uint32_t bhf[2], blf[2];
                ldsm_x2_t(bhf[0], bhf[1], vhB + offBase + nt * 16);
                ldsm_x2_t(blf[0], blf[1], vlB + offBase + nt * 16);
                mma16816(oacc[nt], pah, bhf);
                mma16816(oacc[nt], pah, blf);
                mma16816(oacc[nt], pal, bhf);
            }
        }
    }

    // --- epilogue ---
    const int bb = bh >> 4;
    const int h  = bh & 15;
#pragma unroll
    for (int r = 0; r < 2; r++) {
        float inv = 1.f / lrow[r];
        int q = q0 + w * 16 + g + 8 * r;
        float* dst = g_O + ((size_t)(bb * SEQ + q)) * DMOD + h * DK;
#pragma unroll
        for (int nt = 0; nt < 8; nt++) {
            *(float2*)&dst[nt * 8 + 2 * t] =
                make_float2(oacc[nt][2 * r] * inv, oacc[nt][2 * r + 1] * inv);
        }
    }
}

// ---------------------------------------------------------------------------
extern "C" void kernel_launch(void* const* d_in, const int* in_sizes, int n_in,
                              void* d_out, int out_size)
{
    const float* X  = (const float*)d_in[0];
    const float* Wq = (const float*)d_in[1];
    const float* Wk = (const float*)d_in[2];
    const float* Wv = (const float*)d_in[3];
    const float* Wo = (const float*)d_in[4];
    float* out = (float*)d_out;

    rope_table_kernel<<<SEQ * 32 / 256, 256>>>();

    // fused QKV projections: grid.x = 3 * 16 n-tiles
    gemm_mma_kernel<<<dim3(48, MROWS / 128), 256>>>(X, Wq, Wk, Wv, nullptr, -1);

    attn_mma_kernel<<<dim3(SEQ / 64, BATCH * NH), 128>>>();

    gemm_mma_kernel<<<dim3(16, MROWS / 128), 256>>>(X, Wo, Wo, Wo, out, 3);
}

// round 10
// speedup vs baseline: 1.3576x; 1.1043x over previous
#include <cuda_runtime.h>
#include <cuda_bf16.h>
#include <math.h>
#include <stdint.h>

// Problem constants
#define BATCH 2
#define SEQ   2048
#define DMOD  1024
#define NH    16
#define DK    64
#define MROWS (BATCH*SEQ)   // 4096

// Scratch (allocation-free per harness rules)
__device__ float g_Q[BATCH*NH*SEQ*DK];   // [b][h][s][dk], post-RoPE
__device__ float g_K[BATCH*NH*SEQ*DK];   // [b][h][s][dk], post-RoPE
__device__ float g_V[BATCH*NH*SEQ*DK];   // [b][h][s][dk]
__device__ float g_O[MROWS*DMOD];        // [b][s][h*dk]
__device__ float2 g_cs[SEQ][DK/2];       // (cos, sin) per (pos, pair)

// ---------------------------------------------------------------------------
// helpers
// ---------------------------------------------------------------------------
__device__ __forceinline__ void split2(float e, float o, uint32_t& hi, uint32_t& lo)
{
    __nv_bfloat16 eh = __float2bfloat16(e);
    __nv_bfloat16 oh = __float2bfloat16(o);
    float er  = e - __bfloat162float(eh);
    float orr = o - __bfloat162float(oh);
    __nv_bfloat16 el = __float2bfloat16(er);
    __nv_bfloat16 ol = __float2bfloat16(orr);
    hi = (uint32_t)__bfloat16_as_ushort(eh) | ((uint32_t)__bfloat16_as_ushort(oh) << 16);
    lo = (uint32_t)__bfloat16_as_ushort(el) | ((uint32_t)__bfloat16_as_ushort(ol) << 16);
}

__device__ __forceinline__ void mma16816(float* c, const uint32_t* a, const uint32_t* b)
{
    asm volatile(
        "mma.sync.aligned.m16n8k16.row.col.f32.bf16.bf16.f32 "
        "{%0,%1,%2,%3}, {%4,%5,%6,%7}, {%8,%9}, {%0,%1,%2,%3};\n"
        : "+f"(c[0]), "+f"(c[1]), "+f"(c[2]), "+f"(c[3])
        : "r"(a[0]), "r"(a[1]), "r"(a[2]), "r"(a[3]), "r"(b[0]), "r"(b[1]));
}

__device__ __forceinline__ void ldsm_x4(uint32_t* r, uint32_t addr)
{
    asm volatile("ldmatrix.sync.aligned.m8n8.x4.shared.b16 {%0,%1,%2,%3}, [%4];"
                 : "=r"(r[0]), "=r"(r[1]), "=r"(r[2]), "=r"(r[3]) : "r"(addr));
}
__device__ __forceinline__ void ldsm_x2(uint32_t& r0, uint32_t& r1, uint32_t addr)
{
    asm volatile("ldmatrix.sync.aligned.m8n8.x2.shared.b16 {%0,%1}, [%2];"
                 : "=r"(r0), "=r"(r1) : "r"(addr));
}
__device__ __forceinline__ void ldsm_x2_t(uint32_t& r0, uint32_t& r1, uint32_t addr)
{
    asm volatile("ldmatrix.sync.aligned.m8n8.x2.trans.shared.b16 {%0,%1}, [%2];"
                 : "=r"(r0), "=r"(r1) : "r"(addr));
}

__device__ __forceinline__ void load_split(const float* p, uint32_t* h, uint32_t* l)
{
    float4 v = *(const float4*)p;
    split2(v.x, v.y, h[0], l[0]);
    split2(v.z, v.w, h[1], l[1]);
}

// -------------------------- prep kernel -------------------------------------
__global__ void rope_table_kernel()
{
    int idx = blockIdx.x * blockDim.x + threadIdx.x;      // SEQ*32
    int s = idx >> 5, j = idx & 31;
    float invf = powf(10000.0f, -(float)(2 * j) / 64.0f);
    float ang = (float)s * invf;
    float sn, cs;
    sincosf(ang, &sn, &cs);
    g_cs[s][j] = make_float2(cs, sn);
}

// ---------------------------------------------------------------------------
// Tensor-core GEMM (3xBF16 split): C = A @ W^T, ldmatrix fragment path.
// BM=128, BN=64, BK=32, 256 threads, 8 warps (4x2), warp tile 32x32.
// Smem: row-major bf16, pitch 40 elems (80 B) -> conflict-free ldmatrix.
// mode_in = -1: fused QKV (mode = blockIdx.x>>4)   mode_in = 3: O @ Wo^T
// ---------------------------------------------------------------------------
#define APITCH 40

__global__ __launch_bounds__(256) void gemm_mma_kernel(
    const float* __restrict__ Ain,
    const float* __restrict__ W0, const float* __restrict__ W1,
    const float* __restrict__ W2,
    float* __restrict__ out, int mode_in)
{
    int mode, n0;
    const float* W;
    if (mode_in < 0) {
        mode = (int)blockIdx.x >> 4;
        W = (mode == 0) ? W0 : (mode == 1) ? W1 : W2;
        n0 = ((int)blockIdx.x & 15) * 64;
    } else {
        mode = mode_in;
        W = W0;
        n0 = (int)blockIdx.x * 64;
    }
    const float* A = (mode == 3) ? g_O : Ain;

    __shared__ __nv_bfloat16 sAh[128 * APITCH], sAl[128 * APITCH];
    __shared__ __nv_bfloat16 sBh[64 * APITCH],  sBl[64 * APITCH];

    const int tid  = threadIdx.x;
    const int warp = tid >> 5, lane = tid & 31;
    const int wr = warp >> 1, wc = warp & 1;
    const int g = lane >> 2, t = lane & 3;
    const int m0 = blockIdx.y * 128;

    const uint32_t aHB = (uint32_t)__cvta_generic_to_shared(sAh);
    const uint32_t aLB = (uint32_t)__cvta_generic_to_shared(sAl);
    const uint32_t bHB = (uint32_t)__cvta_generic_to_shared(sBh);
    const uint32_t bLB = (uint32_t)__cvta_generic_to_shared(sBl);

    // ldmatrix per-lane partial offset (row-major, 80B pitch, 16B col halves)
    const uint32_t lmOff = (uint32_t)((lane & 15) * (APITCH * 2) + (lane >> 4) * 16);

    float acc[2][4][4];
#pragma unroll
    for (int mt = 0; mt < 2; mt++)
#pragma unroll
        for (int nt = 0; nt < 4; nt++)
#pragma unroll
            for (int i = 0; i < 4; i++) acc[mt][nt][i] = 0.f;

    // preload index mapping
    int arow[4], akq[4];
#pragma unroll
    for (int i = 0; i < 4; i++) {
        int lin = tid + i * 256;            // 0..1023
        arow[i] = lin >> 3;                 // 0..127
        akq[i]  = (lin & 7) * 4;            // 0,4,...,28
    }
    int brow[2], bkq[2];
#pragma unroll
    for (int i = 0; i < 2; i++) {
        int lin = tid + i * 256;            // 0..511
        brow[i] = lin >> 3;                 // 0..63
        bkq[i]  = (lin & 7) * 4;
    }

    uint32_t pAh[4][2], pAl[4][2], pBh[2][2], pBl[2][2];
#pragma unroll
    for (int i = 0; i < 4; i++)
        load_split(&A[(size_t)(m0 + arow[i]) * DMOD + akq[i]], pAh[i], pAl[i]);
#pragma unroll
    for (int i = 0; i < 2; i++)
        load_split(&W[(size_t)(n0 + brow[i]) * DMOD + bkq[i]], pBh[i], pBl[i]);

    for (int k0 = 0; k0 < DMOD; k0 += 32) {
        __syncthreads();
#pragma unroll
        for (int i = 0; i < 4; i++) {
            int e = arow[i] * APITCH + akq[i];
            *(uint2*)&sAh[e] = make_uint2(pAh[i][0], pAh[i][1]);
            *(uint2*)&sAl[e] = make_uint2(pAl[i][0], pAl[i][1]);
        }
#pragma unroll
        for (int i = 0; i < 2; i++) {
            int e = brow[i] * APITCH + bkq[i];
            *(uint2*)&sBh[e] = make_uint2(pBh[i][0], pBh[i][1]);
            *(uint2*)&sBl[e] = make_uint2(pBl[i][0], pBl[i][1]);
        }
        __syncthreads();

        // preload + split NEXT tile (overlaps with MMA phase)
        if (k0 + 32 < DMOD) {
            int kn = k0 + 32;
#pragma unroll
            for (int i = 0; i < 4; i++)
                load_split(&A[(size_t)(m0 + arow[i]) * DMOD + kn + akq[i]],
                           pAh[i], pAl[i]);
#pragma unroll
            for (int i = 0; i < 2; i++)
                load_split(&W[(size_t)(n0 + brow[i]) * DMOD + kn + bkq[i]],
                           pBh[i], pBl[i]);
        }

#pragma unroll
        for (int s = 0; s < 2; s++) {
            const uint32_t sB = (uint32_t)(s * 32) + lmOff;   // 16 bf16 = 32B per s

            uint32_t ah[2][4], al[2][4], bh[4][2], bl[4][2];
#pragma unroll
            for (int mt = 0; mt < 2; mt++) {
                uint32_t ro = (uint32_t)((wr * 32 + mt * 16) * (APITCH * 2));
                ldsm_x4(ah[mt], aHB + ro + sB);
                ldsm_x4(al[mt], aLB + ro + sB);
            }
#pragma unroll
            for (int ntp = 0; ntp < 2; ntp++) {
                uint32_t ro = (uint32_t)((wc * 32 + ntp * 16) * (APITCH * 2));
                uint32_t b4[4];
                ldsm_x4(b4, bHB + ro + sB);
                bh[2 * ntp][0] = b4[0];     bh[2 * ntp][1] = b4[2];
                bh[2 * ntp + 1][0] = b4[1]; bh[2 * ntp + 1][1] = b4[3];
                ldsm_x4(b4, bLB + ro + sB);
                bl[2 * ntp][0] = b4[0];     bl[2 * ntp][1] = b4[2];
                bl[2 * ntp + 1][0] = b4[1]; bl[2 * ntp + 1][1] = b4[3];
            }
#pragma unroll
            for (int mt = 0; mt < 2; mt++)
#pragma unroll
                for (int nt = 0; nt < 4; nt++) {
                    mma16816(acc[mt][nt], al[mt], bh[nt]);
                    mma16816(acc[mt][nt], ah[mt], bl[nt]);
                    mma16816(acc[mt][nt], ah[mt], bh[nt]);
                }
        }
    }

    // ------------------------------- epilogue -------------------------------
#pragma unroll
    for (int mt = 0; mt < 2; mt++) {
#pragma unroll
        for (int rh = 0; rh < 2; rh++) {
            int m  = m0 + wr * 32 + mt * 16 + g + rh * 8;
            int bb = m >> 11;
            int ss = m & (SEQ - 1);
#pragma unroll
            for (int nt = 0; nt < 4; nt++) {
                float c0 = acc[mt][nt][rh * 2 + 0];
                float c1 = acc[mt][nt][rh * 2 + 1];
                int n = n0 + wc * 32 + nt * 8 + t * 2;
                if (mode == 3) {
                    *(float2*)&out[(size_t)m * DMOD + n] = make_float2(c0, c1);
                } else if (mode == 2) {
                    int h = n >> 6, i0 = n & 63;
                    *(float2*)&g_V[(((size_t)(bb * NH + h)) * SEQ + ss) * DK + i0] =
                        make_float2(c0, c1);
                } else {
                    int h = n >> 6, i0 = n & 63;
                    float2 cssn = g_cs[ss][i0 >> 1];
                    float r0 = c0 * cssn.x - c1 * cssn.y;
                    float r1 = c1 * cssn.x + c0 * cssn.y;
                    float* dst = ((mode == 0) ? g_Q : g_K)
                               + (((size_t)(bb * NH + h)) * SEQ + ss) * DK + i0;
                    *(float2*)dst = make_float2(r0, r1);
                }
            }
        }
    }
}

// ---------------------------------------------------------------------------
// MMA flash attention (3xBF16 split), causal.  (unchanged, known-good)
// ---------------------------------------------------------------------------
#define VPITCH 72

__global__ __launch_bounds__(128) void attn_mma_kernel()
{
    __shared__ __nv_bfloat16 Ksh[64 * VPITCH];
    __shared__ __nv_bfloat16 Ksl[64 * VPITCH];
    __shared__ __nv_bfloat16 Vsh[64 * VPITCH];
    __shared__ __nv_bfloat16 Vsl[64 * VPITCH];

    const int tid  = threadIdx.x;
    const int w    = tid >> 5;
    const int lane = tid & 31;
    const int g = lane >> 2, t = lane & 3;
    const int qt = (int)gridDim.x - 1 - (int)blockIdx.x;
    const int bh = blockIdx.y;
    const int q0 = qt * 64;

    const float* Qb = g_Q + (size_t)bh * SEQ * DK;
    const float* Kb = g_K + (size_t)bh * SEQ * DK;
    const float* Vb = g_V + (size_t)bh * SEQ * DK;

    uint32_t qh[4][4], ql[4][4];
    {
        const float* Qr0 = Qb + (size_t)(q0 + w * 16 + g) * DK;
        const float* Qr8 = Qr0 + 8 * DK;
#pragma unroll
        for (int ks = 0; ks < 4; ks++) {
            float2 x0 = *(const float2*)&Qr0[ks * 16 + 2 * t];
            float2 x1 = *(const float2*)&Qr8[ks * 16 + 2 * t];
            float2 x2 = *(const float2*)&Qr0[ks * 16 + 8 + 2 * t];
            float2 x3 = *(const float2*)&Qr8[ks * 16 + 8 + 2 * t];
            split2(x0.x, x0.y, qh[ks][0], ql[ks][0]);
            split2(x1.x, x1.y, qh[ks][1], ql[ks][1]);
            split2(x2.x, x2.y, qh[ks][2], ql[ks][2]);
            split2(x3.x, x3.y, qh[ks][3], ql[ks][3]);
        }
    }

    const uint32_t khB = (uint32_t)__cvta_generic_to_shared(Ksh);
    const uint32_t klB = (uint32_t)__cvta_generic_to_shared(Ksl);
    const uint32_t vhB = (uint32_t)__cvta_generic_to_shared(Vsh);
    const uint32_t vlB = (uint32_t)__cvta_generic_to_shared(Vsl);
    const uint32_t kPart = ((lane & 7) * VPITCH + 8 * ((lane >> 3) & 1)) * 2;
    const uint32_t vPart = (((lane & 7) + 8 * ((lane >> 3) & 1)) * VPITCH) * 2;

    float oacc[8][4];
#pragma unroll
    for (int nt = 0; nt < 8; nt++)
#pragma unroll
        for (int i = 0; i < 4; i++) oacc[nt][i] = 0.f;
    float mrow[2] = {-1e30f, -1e30f};
    float lrow[2] = {0.f, 0.f};

    for (int kt = 0; kt <= qt; kt++) {
        __syncthreads();
#pragma unroll
        for (int i = 0; i < 8; i++) {
            int lin = i * 128 + tid;
            int row = lin >> 4;
            int c4  = (lin & 15) * 4;
            const float* src = Kb + (size_t)(kt * 64 + row) * DK + c4;
            float4 v = *(const float4*)src;
            uint32_t h0, l0, h1, l1;
            split2(v.x, v.y, h0, l0);
            split2(v.z, v.w, h1, l1);
            *(uint32_t*)&Ksh[row * VPITCH + c4]     = h0;
            *(uint32_t*)&Ksh[row * VPITCH + c4 + 2] = h1;
            *(uint32_t*)&Ksl[row * VPITCH + c4]     = l0;
            *(uint32_t*)&Ksl[row * VPITCH + c4 + 2] = l1;

            const float* sv = Vb + (size_t)(kt * 64 + row) * DK + c4;
            float4 vv = *(const float4*)sv;
            split2(vv.x, vv.y, h0, l0);
            split2(vv.z, vv.w, h1, l1);
            *(uint32_t*)&Vsh[row * VPITCH + c4]     = h0;
            *(uint32_t*)&Vsh[row * VPITCH + c4 + 2] = h1;
            *(uint32_t*)&Vsl[row * VPITCH + c4]     = l0;
            *(uint32_t*)&Vsl[row * VPITCH + c4 + 2] = l1;
        }
        __syncthreads();

        float sacc[8][4];
#pragma unroll
        for (int nt = 0; nt < 8; nt++) {
#pragma unroll
            for (int i = 0; i < 4; i++) sacc[nt][i] = 0.f;
            const uint32_t offBase = (uint32_t)(nt * 8 * VPITCH * 2) + kPart;
#pragma unroll
            for (int ks = 0; ks < 4; ks++) {
                uint32_t bhf[2], blf[2];
                ldsm_x2(bhf[0], bhf[1], khB + offBase + ks * 32);
                ldsm_x2(blf[0], blf[1], klB + offBase + ks * 32);
                mma16816(sacc[nt], ql[ks], bhf);
                mma16816(sacc[nt], qh[ks], blf);
                mma16816(sacc[nt], qh[ks], bhf);
            }
        }

#pragma unroll
        for (int nt = 0; nt < 8; nt++)
#pragma unroll
            for (int i = 0; i < 4; i++) sacc[nt][i] *= 0.125f;
        if (kt == qt) {
#pragma unroll
            for (int nt = 0; nt < 8; nt++)
#pragma unroll
                for (int i = 0; i < 4; i++) {
                    int col = nt * 8 + 2 * t + (i & 1);
                    int row = w * 16 + g + 8 * (i >> 1);
                    if (col > row) sacc[nt][i] = -1e30f;
                }
        }

#pragma unroll
        for (int r = 0; r < 2; r++) {
            float mx = -1e30f;
#pragma unroll
            for (int nt = 0; nt < 8; nt++) {
                mx = fmaxf(mx, sacc[nt][2 * r]);
                mx = fmaxf(mx, sacc[nt][2 * r + 1]);
            }
            mx = fmaxf(mx, __shfl_xor_sync(0xffffffffu, mx, 1));
            mx = fmaxf(mx, __shfl_xor_sync(0xffffffffu, mx, 2));
            float mnew = fmaxf(mrow[r], mx);
            float corr = __expf(mrow[r] - mnew);
            mrow[r] = mnew;
            float rs = 0.f;
#pragma unroll
            for (int nt = 0; nt < 8; nt++) {
                float p0 = __expf(sacc[nt][2 * r]     - mnew);
                float p1 = __expf(sacc[nt][2 * r + 1] - mnew);
                sacc[nt][2 * r] = p0; sacc[nt][2 * r + 1] = p1;
                rs += p0 + p1;
            }
            rs += __shfl_xor_sync(0xffffffffu, rs, 1);
            rs += __shfl_xor_sync(0xffffffffu, rs, 2);
            lrow[r] = lrow[r] * corr + rs;
#pragma unroll
            for (int nt = 0; nt < 8; nt++) {
                oacc[nt][2 * r]     *= corr;
                oacc[nt][2 * r + 1] *= corr;
            }
        }

#pragma unroll
        for (int kc = 0; kc < 4; kc++) {
            uint32_t pah[4], pal[4];
            split2(sacc[2 * kc][0],     sacc[2 * kc][1],     pah[0], pal[0]);
            split2(sacc[2 * kc][2],     sacc[2 * kc][3],     pah[1], pal[1]);
            split2(sacc[2 * kc + 1][0], sacc[2 * kc + 1][1], pah[2], pal[2]);
            split2(sacc[2 * kc + 1][2], sacc[2 * kc + 1][3], pah[3], pal[3]);
            const uint32_t offBase = (uint32_t)(kc * 16 * VPITCH * 2) + vPart;
#pragma unroll
            for (int nt = 0; nt < 8; nt++) {
                uint32_t bhf[2], blf[2];
                ldsm_x2_t(bhf[0], bhf[1], vhB + offBase + nt * 16);
                ldsm_x2_t(blf[0], blf[1], vlB + offBase + nt * 16);
                mma16816(oacc[nt], pah, bhf);
                mma16816(oacc[nt], pah, blf);
                mma16816(oacc[nt], pal, bhf);
            }
        }
    }

    const int bb = bh >> 4;
    const int h  = bh & 15;
#pragma unroll
    for (int r = 0; r < 2; r++) {
        float inv = 1.f / lrow[r];
        int q = q0 + w * 16 + g + 8 * r;
        float* dst = g_O + ((size_t)(bb * SEQ + q)) * DMOD + h * DK;
#pragma unroll
        for (int nt = 0; nt < 8; nt++) {
            *(float2*)&dst[nt * 8 + 2 * t] =
                make_float2(oacc[nt][2 * r] * inv, oacc[nt][2 * r + 1] * inv);
        }
    }
}

// ---------------------------------------------------------------------------
extern "C" void kernel_launch(void* const* d_in, const int* in_sizes, int n_in,
                              void* d_out, int out_size)
{
    const float* X  = (const float*)d_in[0];
    const float* Wq = (const float*)d_in[1];
    const float* Wk = (const float*)d_in[2];
    const float* Wv = (const float*)d_in[3];
    const float* Wo = (const float*)d_in[4];
    float* out = (float*)d_out;

    rope_table_kernel<<<SEQ * 32 / 256, 256>>>();

    gemm_mma_kernel<<<dim3(48, MROWS / 128), 256>>>(X, Wq, Wk, Wv, nullptr, -1);

    attn_mma_kernel<<<dim3(SEQ / 64, BATCH * NH), 128>>>();

    gemm_mma_kernel<<<dim3(16, MROWS / 128), 256>>>(X, Wo, Wo, Wo, out, 3);
}

// round 12
// speedup vs baseline: 1.4489x; 1.0673x over previous
#include <cuda_runtime.h>
#include <cuda_bf16.h>
#include <math.h>
#include <stdint.h>

// Problem constants
#define BATCH 2
#define SEQ   2048
#define DMOD  1024
#define NH    16
#define DK    64
#define MROWS (BATCH*SEQ)   // 4096

// ------------------------- global scratch (no allocs) -----------------------
__device__ float g_Q[BATCH*NH*SEQ*DK];   // post-RoPE fp32 (attention input)
__device__ float g_K[BATCH*NH*SEQ*DK];
__device__ float g_V[BATCH*NH*SEQ*DK];
__device__ __nv_bfloat16 g_Xh[MROWS*DMOD],  g_Xl[MROWS*DMOD];
__device__ __nv_bfloat16 g_Wh[4*DMOD*DMOD], g_Wl[4*DMOD*DMOD];
__device__ __nv_bfloat16 g_Oh[MROWS*DMOD],  g_Ol[MROWS*DMOD];
__device__ float2 g_cs[SEQ][DK/2];       // (cos, sin) per (pos, pair)

// ------------------------------- helpers ------------------------------------
__device__ __forceinline__ void split2(float e, float o, uint32_t& hi, uint32_t& lo)
{
    __nv_bfloat16 eh = __float2bfloat16(e);
    __nv_bfloat16 oh = __float2bfloat16(o);
    float er  = e - __bfloat162float(eh);
    float orr = o - __bfloat162float(oh);
    __nv_bfloat16 el = __float2bfloat16(er);
    __nv_bfloat16 ol = __float2bfloat16(orr);
    hi = (uint32_t)__bfloat16_as_ushort(eh) | ((uint32_t)__bfloat16_as_ushort(oh) << 16);
    lo = (uint32_t)__bfloat16_as_ushort(el) | ((uint32_t)__bfloat16_as_ushort(ol) << 16);
}

__device__ __forceinline__ void mma16816(float* c, const uint32_t* a, const uint32_t* b)
{
    asm volatile(
        "mma.sync.aligned.m16n8k16.row.col.f32.bf16.bf16.f32 "
        "{%0,%1,%2,%3}, {%4,%5,%6,%7}, {%8,%9}, {%0,%1,%2,%3};\n"
        : "+f"(c[0]), "+f"(c[1]), "+f"(c[2]), "+f"(c[3])
        : "r"(a[0]), "r"(a[1]), "r"(a[2]), "r"(a[3]), "r"(b[0]), "r"(b[1]));
}
__device__ __forceinline__ void ldsm_x4(uint32_t* r, uint32_t addr)
{
    asm volatile("ldmatrix.sync.aligned.m8n8.x4.shared.b16 {%0,%1,%2,%3}, [%4];"
                 : "=r"(r[0]), "=r"(r[1]), "=r"(r[2]), "=r"(r[3]) : "r"(addr));
}
__device__ __forceinline__ void ldsm_x2(uint32_t& r0, uint32_t& r1, uint32_t addr)
{
    asm volatile("ldmatrix.sync.aligned.m8n8.x2.shared.b16 {%0,%1}, [%2];"
                 : "=r"(r0), "=r"(r1) : "r"(addr));
}
__device__ __forceinline__ void ldsm_x2_t(uint32_t& r0, uint32_t& r1, uint32_t addr)
{
    asm volatile("ldmatrix.sync.aligned.m8n8.x2.trans.shared.b16 {%0,%1}, [%2];"
                 : "=r"(r0), "=r"(r1) : "r"(addr));
}
__device__ __forceinline__ void cpa16(uint32_t dst, const void* src)
{
    asm volatile("cp.async.cg.shared.global [%0], [%1], 16;" :: "r"(dst), "l"(src));
}
template<int N> __device__ __forceinline__ void cp_wait()
{
    asm volatile("cp.async.wait_group %0;" :: "n"(N) : "memory");
}

// -------------------------- prep kernels ------------------------------------
__global__ void rope_table_kernel()
{
    int idx = blockIdx.x * blockDim.x + threadIdx.x;      // SEQ*32
    int s = idx >> 5, j = idx & 31;
    float invf = powf(10000.0f, -(float)(2 * j) / 64.0f);
    float ang = (float)s * invf;
    float sn, cs;
    sincosf(ang, &sn, &cs);
    g_cs[s][j] = make_float2(cs, sn);
}

__global__ void split_kernel(const float* __restrict__ src, int sel, int n4)
{
    int i = blockIdx.x * blockDim.x + threadIdx.x;
    if (i >= n4) return;
    __nv_bfloat16 *h, *l;
    if (sel == 0) { h = g_Xh; l = g_Xl; }
    else { h = g_Wh + (size_t)(sel - 1) * DMOD * DMOD;
           l = g_Wl + (size_t)(sel - 1) * DMOD * DMOD; }
    float4 v = ((const float4*)src)[i];
    uint32_t h0, l0, h1, l1;
    split2(v.x, v.y, h0, l0);
    split2(v.z, v.w, h1, l1);
    *(uint32_t*)&h[4 * i]     = h0;
    *(uint32_t*)&h[4 * i + 2] = h1;
    *(uint32_t*)&l[4 * i]     = l0;
    *(uint32_t*)&l[4 * i + 2] = l1;
}

// ---------------------------------------------------------------------------
// Tensor-core GEMM (3xBF16 split, PRE-SPLIT inputs, cp.async double-buffered).
// C[m][n] = sum_k A[m][k]*W[n][k].  BM=128, BN=64, BK=32, 256 thr, 8 warps.
// Smem: row-major bf16, pitch 40 elems (80 B) -> conflict-free ldmatrix.
// mode_in = -1: fused QKV (mode = bx>>4, n0=(bx&15)*64)   mode_in = 3: O@Wo^T
// ---------------------------------------------------------------------------
#define APITCH   40
#define SA_B     (128*APITCH*2)            // 10240
#define SB_B     (64*APITCH*2)             // 5120
#define STG_B    (2*SA_B + 2*SB_B)         // 30720
#define GSM_TOT  (2*STG_B)                 // 61440

__global__ __launch_bounds__(256) void gemm_mma_kernel(
    float* __restrict__ out, int mode_in)
{
    extern __shared__ char sm[];
    const uint32_t smB = (uint32_t)__cvta_generic_to_shared(sm);

    int mode, n0;
    if (mode_in < 0) { mode = (int)blockIdx.x >> 4; n0 = ((int)blockIdx.x & 15) * 64; }
    else             { mode = 3;                    n0 = (int)blockIdx.x * 64; }
    const int m0 = (int)blockIdx.y * 128;

    const __nv_bfloat16* Ah = (mode == 3) ? g_Oh : g_Xh;
    const __nv_bfloat16* Al = (mode == 3) ? g_Ol : g_Xl;
    const __nv_bfloat16* Wh = g_Wh + (size_t)mode * DMOD * DMOD;
    const __nv_bfloat16* Wl = g_Wl + (size_t)mode * DMOD * DMOD;

    const int tid  = threadIdx.x;
    const int warp = tid >> 5, lane = tid & 31;
    const int wr = warp >> 1, wc = warp & 1;
    const int g = lane >> 2, t = lane & 3;

    // cp.async mapping: A 512 chunks of 16B (2/thread), B 256 chunks (1/thread)
    const int ar0 = tid >> 2,         ao0 = tid & 3;          // chunk tid
    const int ar1 = (tid + 256) >> 2, ao1 = (tid + 256) & 3;  // chunk tid+256
    const int br  = tid >> 2,         bo  = tid & 3;

    auto issue = [&](int kc, int stg) {
        const int k0 = kc * 32;
        const uint32_t aH = smB + stg * STG_B;
        const uint32_t aL = aH + SA_B;
        const uint32_t bH = aL + SA_B;
        const uint32_t bL = bH + SB_B;
        cpa16(aH + ar0 * 80 + ao0 * 16, Ah + (size_t)(m0 + ar0) * DMOD + k0 + ao0 * 8);
        cpa16(aH + ar1 * 80 + ao1 * 16, Ah + (size_t)(m0 + ar1) * DMOD + k0 + ao1 * 8);
        cpa16(aL + ar0 * 80 + ao0 * 16, Al + (size_t)(m0 + ar0) * DMOD + k0 + ao0 * 8);
        cpa16(aL + ar1 * 80 + ao1 * 16, Al + (size_t)(m0 + ar1) * DMOD + k0 + ao1 * 8);
        cpa16(bH + br * 80 + bo * 16,   Wh + (size_t)(n0 + br) * DMOD + k0 + bo * 8);
        cpa16(bL + br * 80 + bo * 16,   Wl + (size_t)(n0 + br) * DMOD + k0 + bo * 8);
        asm volatile("cp.async.commit_group;\n" ::);
    };

    // ldmatrix per-lane partial offset (row-major, 80B pitch, 16B col halves)
    const uint32_t lmOff = (uint32_t)((lane & 15) * 80 + (lane >> 4) * 16);

    float acc[2][4][4];
#pragma unroll
    for (int mt = 0; mt < 2; mt++)
#pragma unroll
        for (int nt = 0; nt < 4; nt++)
#pragma unroll
            for (int i = 0; i < 4; i++) acc[mt][nt][i] = 0.f;

    issue(0, 0);
    issue(1, 1);

    for (int kc = 0; kc < 32; kc++) {
        if (kc < 31) cp_wait<1>(); else cp_wait<0>();
        __syncthreads();

        const int stg = kc & 1;
        const uint32_t aHB = smB + stg * STG_B;
        const uint32_t aLB = aHB + SA_B;
        const uint32_t bHB = aLB + SA_B;
        const uint32_t bLB = bHB + SB_B;

#pragma unroll
        for (int s = 0; s < 2; s++) {
            const uint32_t sB = (uint32_t)(s * 32) + lmOff;

            uint32_t ah[2][4], al[2][4], bh[4][2], bl[4][2];
#pragma unroll
            for (int mt = 0; mt < 2; mt++) {
                uint32_t ro = (uint32_t)((wr * 32 + mt * 16) * 80);
                ldsm_x4(ah[mt], aHB + ro + sB);
                ldsm_x4(al[mt], aLB + ro + sB);
            }
#pragma unroll
            for (int ntp = 0; ntp < 2; ntp++) {
                uint32_t ro = (uint32_t)((wc * 32 + ntp * 16) * 80);
                uint32_t b4[4];
                ldsm_x4(b4, bHB + ro + sB);
                bh[2 * ntp][0] = b4[0];     bh[2 * ntp][1] = b4[2];
                bh[2 * ntp + 1][0] = b4[1]; bh[2 * ntp + 1][1] = b4[3];
                ldsm_x4(b4, bLB + ro + sB);
                bl[2 * ntp][0] = b4[0];     bl[2 * ntp][1] = b4[2];
                bl[2 * ntp + 1][0] = b4[1]; bl[2 * ntp + 1][1] = b4[3];
            }
#pragma unroll
            for (int mt = 0; mt < 2; mt++)
#pragma unroll
                for (int nt = 0; nt < 4; nt++) {
                    mma16816(acc[mt][nt], al[mt], bh[nt]);
                    mma16816(acc[mt][nt], ah[mt], bl[nt]);
                    mma16816(acc[mt][nt], ah[mt], bh[nt]);
                }
        }
        __syncthreads();
        if (kc + 2 < 32) issue(kc + 2, stg);
    }

    // ------------------------------- epilogue -------------------------------
#pragma unroll
    for (int mt = 0; mt < 2; mt++) {
#pragma unroll
        for (int rh = 0; rh < 2; rh++) {
            int m  = m0 + wr * 32 + mt * 16 + g + rh * 8;
            int bb = m >> 11;
            int ss = m & (SEQ - 1);
#pragma unroll
            for (int nt = 0; nt < 4; nt++) {
                float c0 = acc[mt][nt][rh * 2 + 0];
                float c1 = acc[mt][nt][rh * 2 + 1];
                int n = n0 + wc * 32 + nt * 8 + t * 2;
                if (mode == 3) {
                    *(float2*)&out[(size_t)m * DMOD + n] = make_float2(c0, c1);
                } else if (mode == 2) {
                    int h = n >> 6, i0 = n & 63;
                    *(float2*)&g_V[(((size_t)(bb * NH + h)) * SEQ + ss) * DK + i0] =
                        make_float2(c0, c1);
                } else {
                    int h = n >> 6, i0 = n & 63;
                    float2 cssn = g_cs[ss][i0 >> 1];
                    float r0 = c0 * cssn.x - c1 * cssn.y;
                    float r1 = c1 * cssn.x + c0 * cssn.y;
                    float* dst = ((mode == 0) ? g_Q : g_K)
                               + (((size_t)(bb * NH + h)) * SEQ + ss) * DK + i0;
                    *(float2*)dst = make_float2(r0, r1);
                }
            }
        }
    }
}

// ---------------------------------------------------------------------------
// MMA flash attention (3xBF16 split), causal. (R10 known-good; epilogue now
// writes split bf16 O for the pre-split Wo GEMM.)
// ---------------------------------------------------------------------------
#define VPITCH 72

__global__ __launch_bounds__(128) void attn_mma_kernel()
{
    __shared__ __nv_bfloat16 Ksh[64 * VPITCH];
    __shared__ __nv_bfloat16 Ksl[64 * VPITCH];
    __shared__ __nv_bfloat16 Vsh[64 * VPITCH];
    __shared__ __nv_bfloat16 Vsl[64 * VPITCH];

    const int tid  = threadIdx.x;
    const int w    = tid >> 5;
    const int lane = tid & 31;
    const int g = lane >> 2, t = lane & 3;
    const int qt = (int)gridDim.x - 1 - (int)blockIdx.x;
    const int bh = blockIdx.y;
    const int q0 = qt * 64;

    const float* Qb = g_Q + (size_t)bh * SEQ * DK;
    const float* Kb = g_K + (size_t)bh * SEQ * DK;
    const float* Vb = g_V + (size_t)bh * SEQ * DK;

    uint32_t qh[4][4], ql[4][4];
    {
        const float* Qr0 = Qb + (size_t)(q0 + w * 16 + g) * DK;
        const float* Qr8 = Qr0 + 8 * DK;
#pragma unroll
        for (int ks = 0; ks < 4; ks++) {
            float2 x0 = *(const float2*)&Qr0[ks * 16 + 2 * t];
            float2 x1 = *(const float2*)&Qr8[ks * 16 + 2 * t];
            float2 x2 = *(const float2*)&Qr0[ks * 16 + 8 + 2 * t];
            float2 x3 = *(const float2*)&Qr8[ks * 16 + 8 + 2 * t];
            split2(x0.x, x0.y, qh[ks][0], ql[ks][0]);
            split2(x1.x, x1.y, qh[ks][1], ql[ks][1]);
            split2(x2.x, x2.y, qh[ks][2], ql[ks][2]);
            split2(x3.x, x3.y, qh[ks][3], ql[ks][3]);
        }
    }

    const uint32_t khB = (uint32_t)__cvta_generic_to_shared(Ksh);
    const uint32_t klB = (uint32_t)__cvta_generic_to_shared(Ksl);
    const uint32_t vhB = (uint32_t)__cvta_generic_to_shared(Vsh);
    const uint32_t vlB = (uint32_t)__cvta_generic_to_shared(Vsl);
    const uint32_t kPart = ((lane & 7) * VPITCH + 8 * ((lane >> 3) & 1)) * 2;
    const uint32_t vPart = (((lane & 7) + 8 * ((lane >> 3) & 1)) * VPITCH) * 2;

    float oacc[8][4];
#pragma unroll
    for (int nt = 0; nt < 8; nt++)
#pragma unroll
        for (int i = 0; i < 4; i++) oacc[nt][i] = 0.f;
    float mrow[2] = {-1e30f, -1e30f};
    float lrow[2] = {0.f, 0.f};

    for (int kt = 0; kt <= qt; kt++) {
        __syncthreads();
#pragma unroll
        for (int i = 0; i < 8; i++) {
            int lin = i * 128 + tid;
            int row = lin >> 4;
            int c4  = (lin & 15) * 4;
            const float* src = Kb + (size_t)(kt * 64 + row) * DK + c4;
            float4 v = *(const float4*)src;
            uint32_t h0, l0, h1, l1;
            split2(v.x, v.y, h0, l0);
            split2(v.z, v.w, h1, l1);
            *(uint32_t*)&Ksh[row * VPITCH + c4]     = h0;
            *(uint32_t*)&Ksh[row * VPITCH + c4 + 2] = h1;
            *(uint32_t*)&Ksl[row * VPITCH + c4]     = l0;
            *(uint32_t*)&Ksl[row * VPITCH + c4 + 2] = l1;

            const float* sv = Vb + (size_t)(kt * 64 + row) * DK + c4;
            float4 vv = *(const float4*)sv;
            split2(vv.x, vv.y, h0, l0);
            split2(vv.z, vv.w, h1, l1);
            *(uint32_t*)&Vsh[row * VPITCH + c4]     = h0;
            *(uint32_t*)&Vsh[row * VPITCH + c4 + 2] = h1;
            *(uint32_t*)&Vsl[row * VPITCH + c4]     = l0;
            *(uint32_t*)&Vsl[row * VPITCH + c4 + 2] = l1;
        }
        __syncthreads();

        float sacc[8][4];
#pragma unroll
        for (int nt = 0; nt < 8; nt++) {
#pragma unroll
            for (int i = 0; i < 4; i++) sacc[nt][i] = 0.f;
            const uint32_t offBase = (uint32_t)(nt * 8 * VPITCH * 2) + kPart;
#pragma unroll
            for (int ks = 0; ks < 4; ks++) {
                uint32_t bhf[2], blf[2];
                ldsm_x2(bhf[0], bhf[1], khB + offBase + ks * 32);
                ldsm_x2(blf[0], blf[1], klB + offBase + ks * 32);
                mma16816(sacc[nt], ql[ks], bhf);
                mma16816(sacc[nt], qh[ks], blf);
                mma16816(sacc[nt], qh[ks], bhf);
            }
        }

#pragma unroll
        for (int nt = 0; nt < 8; nt++)
#pragma unroll
            for (int i = 0; i < 4; i++) sacc[nt][i] *= 0.125f;
        if (kt == qt) {
#pragma unroll
            for (int nt = 0; nt < 8; nt++)
#pragma unroll
                for (int i = 0; i < 4; i++) {
                    int col = nt * 8 + 2 * t + (i & 1);
                    int row = w * 16 + g + 8 * (i >> 1);
                    if (col > row) sacc[nt][i] = -1e30f;
                }
        }

#pragma unroll
        for (int r = 0; r < 2; r++) {
            float mx = -1e30f;
#pragma unroll
            for (int nt = 0; nt < 8; nt++) {
                mx = fmaxf(mx, sacc[nt][2 * r]);
                mx = fmaxf(mx, sacc[nt][2 * r + 1]);
            }
            mx = fmaxf(mx, __shfl_xor_sync(0xffffffffu, mx, 1));
            mx = fmaxf(mx, __shfl_xor_sync(0xffffffffu, mx, 2));
            float mnew = fmaxf(mrow[r], mx);
            float corr = __expf(mrow[r] - mnew);
            mrow[r] = mnew;
            float rs = 0.f;
#pragma unroll
            for (int nt = 0; nt < 8; nt++) {
                float p0 = __expf(sacc[nt][2 * r]     - mnew);
                float p1 = __expf(sacc[nt][2 * r + 1] - mnew);
                sacc[nt][2 * r] = p0; sacc[nt][2 * r + 1] = p1;
                rs += p0 + p1;
            }
            rs += __shfl_xor_sync(0xffffffffu, rs, 1);
            rs += __shfl_xor_sync(0xffffffffu, rs, 2);
            lrow[r] = lrow[r] * corr + rs;
#pragma unroll
            for (int nt = 0; nt < 8; nt++) {
                oacc[nt][2 * r]     *= corr;
                oacc[nt][2 * r + 1] *= corr;
            }
        }

#pragma unroll
        for (int kc = 0; kc < 4; kc++) {
            uint32_t pah[4], pal[4];
            split2(sacc[2 * kc][0],     sacc[2 * kc][1],     pah[0], pal[0]);
            split2(sacc[2 * kc][2],     sacc[2 * kc][3],     pah[1], pal[1]);
            split2(sacc[2 * kc + 1][0], sacc[2 * kc + 1][1], pah[2], pal[2]);
            split2(sacc[2 * kc + 1][2], sacc[2 * kc + 1][3], pah[3], pal[3]);
            const uint32_t offBase = (uint32_t)(kc * 16 * VPITCH * 2) + vPart;
#pragma unroll
            for (int nt = 0; nt < 8; nt++) {
                uint32_t bhf[2], blf[2];
                ldsm_x2_t(bhf[0], bhf[1], vhB + offBase + nt * 16);
                ldsm_x2_t(blf[0], blf[1], vlB + offBase + nt * 16);
                mma16816(oacc[nt], pah, bhf);
                mma16816(oacc[nt], pah, blf);
                mma16816(oacc[nt], pal, bhf);
            }
        }
    }

    // epilogue: write SPLIT O (bf16 hi/lo) for the pre-split Wo GEMM
    const int bb = bh >> 4;
    const int h  = bh & 15;
#pragma unroll
    for (int r = 0; r < 2; r++) {
        float inv = 1.f / lrow[r];
        int q = q0 + w * 16 + g + 8 * r;
        size_t rowoff = ((size_t)(bb * SEQ + q)) * DMOD + h * DK;
#pragma unroll
        for (int nt = 0; nt < 8; nt++) {
            uint32_t hi, lo;
            split2(oacc[nt][2 * r] * inv, oacc[nt][2 * r + 1] * inv, hi, lo);
            *(uint32_t*)&g_Oh[rowoff + nt * 8 + 2 * t] = hi;
            *(uint32_t*)&g_Ol[rowoff + nt * 8 + 2 * t] = lo;
        }
    }
}

// ---------------------------------------------------------------------------
extern "C" void kernel_launch(void* const* d_in, const int* in_sizes, int n_in,
                              void* d_out, int out_size)
{
    const float* X  = (const float*)d_in[0];
    const float* Wq = (const float*)d_in[1];
    const float* Wk = (const float*)d_in[2];
    const float* Wv = (const float*)d_in[3];
    const float* Wo = (const float*)d_in[4];
    float* out = (float*)d_out;

    rope_table_kernel<<<SEQ * 32 / 256, 256>>>();
    split_kernel<<<MROWS * DMOD / 4 / 256, 256>>>(X,  0, MROWS * DMOD / 4);
    split_kernel<<<DMOD * DMOD / 4 / 256, 256>>>(Wq, 1, DMOD * DMOD / 4);
    split_kernel<<<DMOD * DMOD / 4 / 256, 256>>>(Wk, 2, DMOD * DMOD / 4);
    split_kernel<<<DMOD * DMOD / 4 / 256, 256>>>(Wv, 3, DMOD * DMOD / 4);
    split_kernel<<<DMOD * DMOD / 4 / 256, 256>>>(Wo, 4, DMOD * DMOD / 4);

    cudaFuncSetAttribute(gemm_mma_kernel,
                         cudaFuncAttributeMaxDynamicSharedMemorySize, GSM_TOT);

    // fused QKV: grid.x = 3 modes * 16 n-tiles
    gemm_mma_kernel<<<dim3(48, MROWS / 128), 256, GSM_TOT>>>(nullptr, -1);

    attn_mma_kernel<<<dim3(SEQ / 64, BATCH * NH), 128>>>();

    gemm_mma_kernel<<<dim3(16, MROWS / 128), 256, GSM_TOT>>>(out, 3);
}

// round 13
// speedup vs baseline: 1.5782x; 1.0893x over previous
#include <cuda_runtime.h>
#include <cuda_bf16.h>
#include <math.h>
#include <stdint.h>

// Problem constants
#define BATCH 2
#define SEQ   2048
#define DMOD  1024
#define NH    16
#define DK    64
#define MROWS (BATCH*SEQ)   // 4096

// ------------------------- global scratch (no allocs) -----------------------
__device__ __nv_bfloat16 g_Xh[MROWS*DMOD],  g_Xl[MROWS*DMOD];
__device__ __nv_bfloat16 g_Wh[4*DMOD*DMOD], g_Wl[4*DMOD*DMOD];
__device__ __nv_bfloat16 g_Qh[BATCH*NH*SEQ*DK], g_Ql[BATCH*NH*SEQ*DK];
__device__ __nv_bfloat16 g_Kh[BATCH*NH*SEQ*DK], g_Kl[BATCH*NH*SEQ*DK];
__device__ __nv_bfloat16 g_Vh[BATCH*NH*SEQ*DK], g_Vl[BATCH*NH*SEQ*DK];
__device__ __nv_bfloat16 g_Oh[MROWS*DMOD],  g_Ol[MROWS*DMOD];
__device__ float2 g_cs[SEQ][DK/2];       // (cos, sin) per (pos, pair)

// ------------------------------- helpers ------------------------------------
__device__ __forceinline__ void split2(float e, float o, uint32_t& hi, uint32_t& lo)
{
    __nv_bfloat16 eh = __float2bfloat16(e);
    __nv_bfloat16 oh = __float2bfloat16(o);
    float er  = e - __bfloat162float(eh);
    float orr = o - __bfloat162float(oh);
    __nv_bfloat16 el = __float2bfloat16(er);
    __nv_bfloat16 ol = __float2bfloat16(orr);
    hi = (uint32_t)__bfloat16_as_ushort(eh) | ((uint32_t)__bfloat16_as_ushort(oh) << 16);
    lo = (uint32_t)__bfloat16_as_ushort(el) | ((uint32_t)__bfloat16_as_ushort(ol) << 16);
}

__device__ __forceinline__ void mma16816(float* c, const uint32_t* a, const uint32_t* b)
{
    asm volatile(
        "mma.sync.aligned.m16n8k16.row.col.f32.bf16.bf16.f32 "
        "{%0,%1,%2,%3}, {%4,%5,%6,%7}, {%8,%9}, {%0,%1,%2,%3};\n"
        : "+f"(c[0]), "+f"(c[1]), "+f"(c[2]), "+f"(c[3])
        : "r"(a[0]), "r"(a[1]), "r"(a[2]), "r"(a[3]), "r"(b[0]), "r"(b[1]));
}
__device__ __forceinline__ void ldsm_x4(uint32_t* r, uint32_t addr)
{
    asm volatile("ldmatrix.sync.aligned.m8n8.x4.shared.b16 {%0,%1,%2,%3}, [%4];"
                 : "=r"(r[0]), "=r"(r[1]), "=r"(r[2]), "=r"(r[3]) : "r"(addr));
}
__device__ __forceinline__ void ldsm_x2(uint32_t& r0, uint32_t& r1, uint32_t addr)
{
    asm volatile("ldmatrix.sync.aligned.m8n8.x2.shared.b16 {%0,%1}, [%2];"
                 : "=r"(r0), "=r"(r1) : "r"(addr));
}
__device__ __forceinline__ void ldsm_x2_t(uint32_t& r0, uint32_t& r1, uint32_t addr)
{
    asm volatile("ldmatrix.sync.aligned.m8n8.x2.trans.shared.b16 {%0,%1}, [%2];"
                 : "=r"(r0), "=r"(r1) : "r"(addr));
}
__device__ __forceinline__ void cpa16(uint32_t dst, const void* src)
{
    asm volatile("cp.async.cg.shared.global [%0], [%1], 16;" :: "r"(dst), "l"(src));
}
template<int N> __device__ __forceinline__ void cp_wait()
{
    asm volatile("cp.async.wait_group %0;" :: "n"(N) : "memory");
}

// -------------------------- prep kernels ------------------------------------
__global__ void rope_table_kernel()
{
    int idx = blockIdx.x * blockDim.x + threadIdx.x;      // SEQ*32
    int s = idx >> 5, j = idx & 31;
    float invf = powf(10000.0f, -(float)(2 * j) / 64.0f);
    float ang = (float)s * invf;
    float sn, cs;
    sincosf(ang, &sn, &cs);
    g_cs[s][j] = make_float2(cs, sn);
}

__global__ void split_kernel(const float* __restrict__ src, int sel, int n4)
{
    int i = blockIdx.x * blockDim.x + threadIdx.x;
    if (i >= n4) return;
    __nv_bfloat16 *h, *l;
    if (sel == 0) { h = g_Xh; l = g_Xl; }
    else { h = g_Wh + (size_t)(sel - 1) * DMOD * DMOD;
           l = g_Wl + (size_t)(sel - 1) * DMOD * DMOD; }
    float4 v = ((const float4*)src)[i];
    uint32_t h0, l0, h1, l1;
    split2(v.x, v.y, h0, l0);
    split2(v.z, v.w, h1, l1);
    *(uint32_t*)&h[4 * i]     = h0;
    *(uint32_t*)&h[4 * i + 2] = h1;
    *(uint32_t*)&l[4 * i]     = l0;
    *(uint32_t*)&l[4 * i + 2] = l1;
}

// ---------------------------------------------------------------------------
// Tensor-core GEMM (3xBF16 split, PRE-SPLIT inputs, cp.async double-buffered).
// C[m][n] = sum_k A[m][k]*W[n][k].  BM=128, BN=64, BK=32, 256 thr, 8 warps.
// mode 0/1: +RoPE -> split Q/K   mode 2: -> split V   mode 3: O@Wo^T -> fp32
// ---------------------------------------------------------------------------
#define APITCH   40
#define SA_B     (128*APITCH*2)            // 10240
#define SB_B     (64*APITCH*2)             // 5120
#define STG_B    (2*SA_B + 2*SB_B)         // 30720
#define GSM_TOT  (2*STG_B)                 // 61440

__global__ __launch_bounds__(256) void gemm_mma_kernel(
    float* __restrict__ out, int mode_in)
{
    extern __shared__ char sm[];
    const uint32_t smB = (uint32_t)__cvta_generic_to_shared(sm);

    int mode, n0;
    if (mode_in < 0) { mode = (int)blockIdx.x >> 4; n0 = ((int)blockIdx.x & 15) * 64; }
    else             { mode = 3;                    n0 = (int)blockIdx.x * 64; }
    const int m0 = (int)blockIdx.y * 128;

    const __nv_bfloat16* Ah = (mode == 3) ? g_Oh : g_Xh;
    const __nv_bfloat16* Al = (mode == 3) ? g_Ol : g_Xl;
    const __nv_bfloat16* Wh = g_Wh + (size_t)mode * DMOD * DMOD;
    const __nv_bfloat16* Wl = g_Wl + (size_t)mode * DMOD * DMOD;

    const int tid  = threadIdx.x;
    const int warp = tid >> 5, lane = tid & 31;
    const int wr = warp >> 1, wc = warp & 1;
    const int g = lane >> 2, t = lane & 3;

    const int ar0 = tid >> 2,         ao0 = tid & 3;
    const int ar1 = (tid + 256) >> 2, ao1 = (tid + 256) & 3;
    const int br  = tid >> 2,         bo  = tid & 3;

    auto issue = [&](int kc, int stg) {
        const int k0 = kc * 32;
        const uint32_t aH = smB + stg * STG_B;
        const uint32_t aL = aH + SA_B;
        const uint32_t bH = aL + SA_B;
        const uint32_t bL = bH + SB_B;
        cpa16(aH + ar0 * 80 + ao0 * 16, Ah + (size_t)(m0 + ar0) * DMOD + k0 + ao0 * 8);
        cpa16(aH + ar1 * 80 + ao1 * 16, Ah + (size_t)(m0 + ar1) * DMOD + k0 + ao1 * 8);
        cpa16(aL + ar0 * 80 + ao0 * 16, Al + (size_t)(m0 + ar0) * DMOD + k0 + ao0 * 8);
        cpa16(aL + ar1 * 80 + ao1 * 16, Al + (size_t)(m0 + ar1) * DMOD + k0 + ao1 * 8);
        cpa16(bH + br * 80 + bo * 16,   Wh + (size_t)(n0 + br) * DMOD + k0 + bo * 8);
        cpa16(bL + br * 80 + bo * 16,   Wl + (size_t)(n0 + br) * DMOD + k0 + bo * 8);
        asm volatile("cp.async.commit_group;\n" ::);
    };

    const uint32_t lmOff = (uint32_t)((lane & 15) * 80 + (lane >> 4) * 16);

    float acc[2][4][4];
#pragma unroll
    for (int mt = 0; mt < 2; mt++)
#pragma unroll
        for (int nt = 0; nt < 4; nt++)
#pragma unroll
            for (int i = 0; i < 4; i++) acc[mt][nt][i] = 0.f;

    issue(0, 0);
    issue(1, 1);

    for (int kc = 0; kc < 32; kc++) {
        if (kc < 31) cp_wait<1>(); else cp_wait<0>();
        __syncthreads();

        const int stg = kc & 1;
        const uint32_t aHB = smB + stg * STG_B;
        const uint32_t aLB = aHB + SA_B;
        const uint32_t bHB = aLB + SA_B;
        const uint32_t bLB = bHB + SB_B;

#pragma unroll
        for (int s = 0; s < 2; s++) {
            const uint32_t sB = (uint32_t)(s * 32) + lmOff;

            uint32_t ah[2][4], al[2][4], bh[4][2], bl[4][2];
#pragma unroll
            for (int mt = 0; mt < 2; mt++) {
                uint32_t ro = (uint32_t)((wr * 32 + mt * 16) * 80);
                ldsm_x4(ah[mt], aHB + ro + sB);
                ldsm_x4(al[mt], aLB + ro + sB);
            }
#pragma unroll
            for (int ntp = 0; ntp < 2; ntp++) {
                uint32_t ro = (uint32_t)((wc * 32 + ntp * 16) * 80);
                uint32_t b4[4];
                ldsm_x4(b4, bHB + ro + sB);
                bh[2 * ntp][0] = b4[0];     bh[2 * ntp][1] = b4[2];
                bh[2 * ntp + 1][0] = b4[1]; bh[2 * ntp + 1][1] = b4[3];
                ldsm_x4(b4, bLB + ro + sB);
                bl[2 * ntp][0] = b4[0];     bl[2 * ntp][1] = b4[2];
                bl[2 * ntp + 1][0] = b4[1]; bl[2 * ntp + 1][1] = b4[3];
            }
#pragma unroll
            for (int mt = 0; mt < 2; mt++)
#pragma unroll
                for (int nt = 0; nt < 4; nt++) {
                    mma16816(acc[mt][nt], al[mt], bh[nt]);
                    mma16816(acc[mt][nt], ah[mt], bl[nt]);
                    mma16816(acc[mt][nt], ah[mt], bh[nt]);
                }
        }
        __syncthreads();
        if (kc + 2 < 32) issue(kc + 2, stg);
    }

    // ------------------------------- epilogue -------------------------------
#pragma unroll
    for (int mt = 0; mt < 2; mt++) {
#pragma unroll
        for (int rh = 0; rh < 2; rh++) {
            int m  = m0 + wr * 32 + mt * 16 + g + rh * 8;
            int bb = m >> 11;
            int ss = m & (SEQ - 1);
#pragma unroll
            for (int nt = 0; nt < 4; nt++) {
                float c0 = acc[mt][nt][rh * 2 + 0];
                float c1 = acc[mt][nt][rh * 2 + 1];
                int n = n0 + wc * 32 + nt * 8 + t * 2;
                if (mode == 3) {
                    *(float2*)&out[(size_t)m * DMOD + n] = make_float2(c0, c1);
                } else {
                    int h = n >> 6, i0 = n & 63;
                    size_t idx = (((size_t)(bb * NH + h)) * SEQ + ss) * DK + i0;
                    uint32_t hi, lo;
                    if (mode == 2) {
                        split2(c0, c1, hi, lo);
                        *(uint32_t*)&g_Vh[idx] = hi;
                        *(uint32_t*)&g_Vl[idx] = lo;
                    } else {
                        float2 cssn = g_cs[ss][i0 >> 1];
                        float r0 = c0 * cssn.x - c1 * cssn.y;
                        float r1 = c1 * cssn.x + c0 * cssn.y;
                        split2(r0, r1, hi, lo);
                        if (mode == 0) {
                            *(uint32_t*)&g_Qh[idx] = hi;
                            *(uint32_t*)&g_Ql[idx] = lo;
                        } else {
                            *(uint32_t*)&g_Kh[idx] = hi;
                            *(uint32_t*)&g_Kl[idx] = lo;
                        }
                    }
                }
            }
        }
    }
}

// ---------------------------------------------------------------------------
// MMA flash attention (3xBF16 split), causal.  PRE-SPLIT Q/K/V inputs:
// tile loads are pure cp.async byte copies; no in-loop split math.
// CTA: 64 queries, 4 warps. grid = (SEQ/64, BATCH*NH), block = 128.
// ---------------------------------------------------------------------------
#define VPITCH 72

__global__ __launch_bounds__(128) void attn_mma_kernel()
{
    __shared__ __nv_bfloat16 Ksh[64 * VPITCH];
    __shared__ __nv_bfloat16 Ksl[64 * VPITCH];
    __shared__ __nv_bfloat16 Vsh[64 * VPITCH];
    __shared__ __nv_bfloat16 Vsl[64 * VPITCH];

    const int tid  = threadIdx.x;
    const int w    = tid >> 5;
    const int lane = tid & 31;
    const int g = lane >> 2, t = lane & 3;
    const int qt = (int)gridDim.x - 1 - (int)blockIdx.x;   // heavy blocks first
    const int bh = blockIdx.y;
    const int q0 = qt * 64;

    const size_t hb = (size_t)bh * SEQ * DK;

    // --- Q fragments: direct packed-pair loads from pre-split Q ---
    uint32_t qh[4][4], ql[4][4];
    {
        const __nv_bfloat16* qh0 = g_Qh + hb + (size_t)(q0 + w * 16 + g) * DK;
        const __nv_bfloat16* ql0 = g_Ql + hb + (size_t)(q0 + w * 16 + g) * DK;
#pragma unroll
        for (int ks = 0; ks < 4; ks++) {
            int c = ks * 16 + 2 * t;
            qh[ks][0] = *(const uint32_t*)&qh0[c];
            qh[ks][1] = *(const uint32_t*)&qh0[8 * DK + c];
            qh[ks][2] = *(const uint32_t*)&qh0[c + 8];
            qh[ks][3] = *(const uint32_t*)&qh0[8 * DK + c + 8];
            ql[ks][0] = *(const uint32_t*)&ql0[c];
            ql[ks][1] = *(const uint32_t*)&ql0[8 * DK + c];
            ql[ks][2] = *(const uint32_t*)&ql0[c + 8];
            ql[ks][3] = *(const uint32_t*)&ql0[8 * DK + c + 8];
        }
    }

    const uint32_t khB = (uint32_t)__cvta_generic_to_shared(Ksh);
    const uint32_t klB = (uint32_t)__cvta_generic_to_shared(Ksl);
    const uint32_t vhB = (uint32_t)__cvta_generic_to_shared(Vsh);
    const uint32_t vlB = (uint32_t)__cvta_generic_to_shared(Vsl);
    const uint32_t kPart = ((lane & 7) * VPITCH + 8 * ((lane >> 3) & 1)) * 2;
    const uint32_t vPart = (((lane & 7) + 8 * ((lane >> 3) & 1)) * VPITCH) * 2;

    float oacc[8][4];
#pragma unroll
    for (int nt = 0; nt < 8; nt++)
#pragma unroll
        for (int i = 0; i < 4; i++) oacc[nt][i] = 0.f;
    float mrow[2] = {-1e30f, -1e30f};
    float lrow[2] = {0.f, 0.f};

    for (int kt = 0; kt <= qt; kt++) {
        __syncthreads();
        // --- pure byte-copy tile loads (4 arrays x 4 chunks of 16B/thread) ---
        {
            const size_t tb = hb + (size_t)kt * 64 * DK;
#pragma unroll
            for (int i = 0; i < 4; i++) {
                int c = tid + i * 128;          // 0..511
                int row = c >> 3, o = c & 7;
                uint32_t doff = (uint32_t)(row * (VPITCH * 2) + o * 16);
                size_t   soff = tb + (size_t)row * DK + o * 8;
                cpa16(khB + doff, g_Kh + soff);
                cpa16(klB + doff, g_Kl + soff);
                cpa16(vhB + doff, g_Vh + soff);
                cpa16(vlB + doff, g_Vl + soff);
            }
            asm volatile("cp.async.commit_group;\n" ::);
            cp_wait<0>();
        }
        __syncthreads();

        // --- S = Q K^T ---
        float sacc[8][4];
#pragma unroll
        for (int nt = 0; nt < 8; nt++) {
#pragma unroll
            for (int i = 0; i < 4; i++) sacc[nt][i] = 0.f;
            const uint32_t offBase = (uint32_t)(nt * 8 * VPITCH * 2) + kPart;
#pragma unroll
            for (int ks = 0; ks < 4; ks++) {
                uint32_t bhf[2], blf[2];
                ldsm_x2(bhf[0], bhf[1], khB + offBase + ks * 32);
                ldsm_x2(blf[0], blf[1], klB + offBase + ks * 32);
                mma16816(sacc[nt], ql[ks], bhf);
                mma16816(sacc[nt], qh[ks], blf);
                mma16816(sacc[nt], qh[ks], bhf);
            }
        }

#pragma unroll
        for (int nt = 0; nt < 8; nt++)
#pragma unroll
            for (int i = 0; i < 4; i++) sacc[nt][i] *= 0.125f;
        if (kt == qt) {
#pragma unroll
            for (int nt = 0; nt < 8; nt++)
#pragma unroll
                for (int i = 0; i < 4; i++) {
                    int col = nt * 8 + 2 * t + (i & 1);
                    int row = w * 16 + g + 8 * (i >> 1);
                    if (col > row) sacc[nt][i] = -1e30f;
                }
        }

        // --- online softmax ---
#pragma unroll
        for (int r = 0; r < 2; r++) {
            float mx = -1e30f;
#pragma unroll
            for (int nt = 0; nt < 8; nt++) {
                mx = fmaxf(mx, sacc[nt][2 * r]);
                mx = fmaxf(mx, sacc[nt][2 * r + 1]);
            }
            mx = fmaxf(mx, __shfl_xor_sync(0xffffffffu, mx, 1));
            mx = fmaxf(mx, __shfl_xor_sync(0xffffffffu, mx, 2));
            float mnew = fmaxf(mrow[r], mx);
            float corr = __expf(mrow[r] - mnew);
            mrow[r] = mnew;
            float rs = 0.f;
#pragma unroll
            for (int nt = 0; nt < 8; nt++) {
                float p0 = __expf(sacc[nt][2 * r]     - mnew);
                float p1 = __expf(sacc[nt][2 * r + 1] - mnew);
                sacc[nt][2 * r] = p0; sacc[nt][2 * r + 1] = p1;
                rs += p0 + p1;
            }
            rs += __shfl_xor_sync(0xffffffffu, rs, 1);
            rs += __shfl_xor_sync(0xffffffffu, rs, 2);
            lrow[r] = lrow[r] * corr + rs;
#pragma unroll
            for (int nt = 0; nt < 8; nt++) {
                oacc[nt][2 * r]     *= corr;
                oacc[nt][2 * r + 1] *= corr;
            }
        }

        // --- O += P V ---
#pragma unroll
        for (int kc = 0; kc < 4; kc++) {
            uint32_t pah[4], pal[4];
            split2(sacc[2 * kc][0],     sacc[2 * kc][1],     pah[0], pal[0]);
            split2(sacc[2 * kc][2],     sacc[2 * kc][3],     pah[1], pal[1]);
            split2(sacc[2 * kc + 1][0], sacc[2 * kc + 1][1], pah[2], pal[2]);
            split2(sacc[2 * kc + 1][2], sacc[2 * kc + 1][3], pah[3], pal[3]);
            const uint32_t offBase = (uint32_t)(kc * 16 * VPITCH * 2) + vPart;
#pragma unroll
            for (int nt = 0; nt < 8; nt++) {
                uint32_t bhf[2], blf[2];
                ldsm_x2_t(bhf[0], bhf[1], vhB + offBase + nt * 16);
                ldsm_x2_t(blf[0], blf[1], vlB + offBase + nt * 16);
                mma16816(oacc[nt], pah, bhf);
                mma16816(oacc[nt], pah, blf);
                mma16816(oacc[nt], pal, bhf);
            }
        }
    }

    // epilogue: write SPLIT O (bf16 hi/lo) for the pre-split Wo GEMM
    const int bb = bh >> 4;
    const int h  = bh & 15;
#pragma unroll
    for (int r = 0; r < 2; r++) {
        float inv = 1.f / lrow[r];
        int q = q0 + w * 16 + g + 8 * r;
        size_t rowoff = ((size_t)(bb * SEQ + q)) * DMOD + h * DK;
#pragma unroll
        for (int nt = 0; nt < 8; nt++) {
            uint32_t hi, lo;
            split2(oacc[nt][2 * r] * inv, oacc[nt][2 * r + 1] * inv, hi, lo);
            *(uint32_t*)&g_Oh[rowoff + nt * 8 + 2 * t] = hi;
            *(uint32_t*)&g_Ol[rowoff + nt * 8 + 2 * t] = lo;
        }
    }
}

// ---------------------------------------------------------------------------
extern "C" void kernel_launch(void* const* d_in, const int* in_sizes, int n_in,
                              void* d_out, int out_size)
{
    const float* X  = (const float*)d_in[0];
    const float* Wq = (const float*)d_in[1];
    const float* Wk = (const float*)d_in[2];
    const float* Wv = (const float*)d_in[3];
    const float* Wo = (const float*)d_in[4];
    float* out = (float*)d_out;

    rope_table_kernel<<<SEQ * 32 / 256, 256>>>();
    split_kernel<<<MROWS * DMOD / 4 / 256, 256>>>(X,  0, MROWS * DMOD / 4);
    split_kernel<<<DMOD * DMOD / 4 / 256, 256>>>(Wq, 1, DMOD * DMOD / 4);
    split_kernel<<<DMOD * DMOD / 4 / 256, 256>>>(Wk, 2, DMOD * DMOD / 4);
    split_kernel<<<DMOD * DMOD / 4 / 256, 256>>>(Wv, 3, DMOD * DMOD / 4);
    split_kernel<<<DMOD * DMOD / 4 / 256, 256>>>(Wo, 4, DMOD * DMOD / 4);

    cudaFuncSetAttribute(gemm_mma_kernel,
                         cudaFuncAttributeMaxDynamicSharedMemorySize, GSM_TOT);

    // fused QKV: grid.x = 3 modes * 16 n-tiles
    gemm_mma_kernel<<<dim3(48, MROWS / 128), 256, GSM_TOT>>>(nullptr, -1);

    attn_mma_kernel<<<dim3(SEQ / 64, BATCH * NH), 128>>>();

    gemm_mma_kernel<<<dim3(16, MROWS / 128), 256, GSM_TOT>>>(out, 3);
}

// round 15
// speedup vs baseline: 1.5794x; 1.0007x over previous
#include <cuda_runtime.h>
#include <cuda_bf16.h>
#include <math.h>
#include <stdint.h>

// Problem constants
#define BATCH 2
#define SEQ   2048
#define DMOD  1024
#define NH    16
#define DK    64
#define MROWS (BATCH*SEQ)   // 4096

// ------------------------- global scratch (no allocs) -----------------------
__device__ __nv_bfloat16 g_Xh[MROWS*DMOD],  g_Xl[MROWS*DMOD];
__device__ __nv_bfloat16 g_Wh[4*DMOD*DMOD], g_Wl[4*DMOD*DMOD];
__device__ __nv_bfloat16 g_Qh[BATCH*NH*SEQ*DK], g_Ql[BATCH*NH*SEQ*DK];
__device__ __nv_bfloat16 g_Kh[BATCH*NH*SEQ*DK], g_Kl[BATCH*NH*SEQ*DK];
__device__ __nv_bfloat16 g_Vh[BATCH*NH*SEQ*DK], g_Vl[BATCH*NH*SEQ*DK];
__device__ __nv_bfloat16 g_Oh[MROWS*DMOD],  g_Ol[MROWS*DMOD];
__device__ float2 g_cs[SEQ][DK/2];       // (cos, sin) per (pos, pair)

// ------------------------------- helpers ------------------------------------
__device__ __forceinline__ void split2(float e, float o, uint32_t& hi, uint32_t& lo)
{
    __nv_bfloat16 eh = __float2bfloat16(e);
    __nv_bfloat16 oh = __float2bfloat16(o);
    float er  = e - __bfloat162float(eh);
    float orr = o - __bfloat162float(oh);
    __nv_bfloat16 el = __float2bfloat16(er);
    __nv_bfloat16 ol = __float2bfloat16(orr);
    hi = (uint32_t)__bfloat16_as_ushort(eh) | ((uint32_t)__bfloat16_as_ushort(oh) << 16);
    lo = (uint32_t)__bfloat16_as_ushort(el) | ((uint32_t)__bfloat16_as_ushort(ol) << 16);
}

__device__ __forceinline__ void mma16816(float* c, const uint32_t* a, const uint32_t* b)
{
    asm volatile(
        "mma.sync.aligned.m16n8k16.row.col.f32.bf16.bf16.f32 "
        "{%0,%1,%2,%3}, {%4,%5,%6,%7}, {%8,%9}, {%0,%1,%2,%3};\n"
        : "+f"(c[0]), "+f"(c[1]), "+f"(c[2]), "+f"(c[3])
        : "r"(a[0]), "r"(a[1]), "r"(a[2]), "r"(a[3]), "r"(b[0]), "r"(b[1]));
}
__device__ __forceinline__ void ldsm_x4(uint32_t* r, uint32_t addr)
{
    asm volatile("ldmatrix.sync.aligned.m8n8.x4.shared.b16 {%0,%1,%2,%3}, [%4];"
                 : "=r"(r[0]), "=r"(r[1]), "=r"(r[2]), "=r"(r[3]) : "r"(addr));
}
__device__ __forceinline__ void ldsm_x4_t(uint32_t* r, uint32_t addr)
{
    asm volatile("ldmatrix.sync.aligned.m8n8.x4.trans.shared.b16 {%0,%1,%2,%3}, [%4];"
                 : "=r"(r[0]), "=r"(r[1]), "=r"(r[2]), "=r"(r[3]) : "r"(addr));
}
__device__ __forceinline__ void cpa16(uint32_t dst, const void* src)
{
    asm volatile("cp.async.cg.shared.global [%0], [%1], 16;" :: "r"(dst), "l"(src));
}
template<int N> __device__ __forceinline__ void cp_wait()
{
    asm volatile("cp.async.wait_group %0;" :: "n"(N) : "memory");
}

// -------------------- fused prep kernel (splits + rope) ----------------------
// blocks [0,4096): split X      blocks [4096,8192): split W (1024 per matrix)
// blocks [8192,8448): rope table
__global__ void prep_kernel(const float* __restrict__ X,
                            const float* __restrict__ Wq,
                            const float* __restrict__ Wk,
                            const float* __restrict__ Wv,
                            const float* __restrict__ Wo)
{
    const int b = blockIdx.x;
    if (b < 8192) {
        const float* src;
        __nv_bfloat16 *h, *l;
        int i;
        if (b < 4096) {                                   // X: 4096 blocks
            src = X; h = g_Xh; l = g_Xl;
            i = (b << 8) + threadIdx.x;
        } else {                                          // W: 1024 blocks each
            const int wb  = b - 4096;
            const int sel = wb >> 10;                     // 0..3
            src = (sel == 0) ? Wq : (sel == 1) ? Wk : (sel == 2) ? Wv : Wo;
            h = g_Wh + (size_t)sel * DMOD * DMOD;
            l = g_Wl + (size_t)sel * DMOD * DMOD;
            i = ((wb & 1023) << 8) + threadIdx.x;
        }
        float4 v = ((const float4*)src)[i];
        uint32_t h0, l0, h1, l1;
        split2(v.x, v.y, h0, l0);
        split2(v.z, v.w, h1, l1);
        *(uint32_t*)&h[4 * i]     = h0;
        *(uint32_t*)&h[4 * i + 2] = h1;
        *(uint32_t*)&l[4 * i]     = l0;
        *(uint32_t*)&l[4 * i + 2] = l1;
    } else {
        int idx = ((b - 8192) << 8) + threadIdx.x;        // SEQ*32
        int s = idx >> 5, j = idx & 31;
        float invf = powf(10000.0f, -(float)(2 * j) / 64.0f);
        float ang = (float)s * invf;
        float sn, cs;
        sincosf(ang, &sn, &cs);
        g_cs[s][j] = make_float2(cs, sn);
    }
}

// ---------------------------------------------------------------------------
// Tensor-core GEMM (3xBF16 split, PRE-SPLIT inputs, cp.async double-buffered).
// (R12/R13 known-good, unchanged.)
// ---------------------------------------------------------------------------
#define APITCH   40
#define SA_B     (128*APITCH*2)            // 10240
#define SB_B     (64*APITCH*2)             // 5120
#define STG_B    (2*SA_B + 2*SB_B)         // 30720
#define GSM_TOT  (2*STG_B)                 // 61440

__global__ __launch_bounds__(256) void gemm_mma_kernel(
    float* __restrict__ out, int mode_in)
{
    extern __shared__ char sm[];
    const uint32_t smB = (uint32_t)__cvta_generic_to_shared(sm);

    int mode, n0;
    if (mode_in < 0) { mode = (int)blockIdx.x >> 4; n0 = ((int)blockIdx.x & 15) * 64; }
    else             { mode = 3;                    n0 = (int)blockIdx.x * 64; }
    const int m0 = (int)blockIdx.y * 128;

    const __nv_bfloat16* Ah = (mode == 3) ? g_Oh : g_Xh;
    const __nv_bfloat16* Al = (mode == 3) ? g_Ol : g_Xl;
    const __nv_bfloat16* Wh = g_Wh + (size_t)mode * DMOD * DMOD;
    const __nv_bfloat16* Wl = g_Wl + (size_t)mode * DMOD * DMOD;

    const int tid  = threadIdx.x;
    const int warp = tid >> 5, lane = tid & 31;
    const int wr = warp >> 1, wc = warp & 1;
    const int g = lane >> 2, t = lane & 3;

    const int ar0 = tid >> 2,         ao0 = tid & 3;
    const int ar1 = (tid + 256) >> 2, ao1 = (tid + 256) & 3;
    const int br  = tid >> 2,         bo  = tid & 3;

    auto issue = [&](int kc, int stg) {
        const int k0 = kc * 32;
        const uint32_t aH = smB + stg * STG_B;
        const uint32_t aL = aH + SA_B;
        const uint32_t bH = aL + SA_B;
        const uint32_t bL = bH + SB_B;
        cpa16(aH + ar0 * 80 + ao0 * 16, Ah + (size_t)(m0 + ar0) * DMOD + k0 + ao0 * 8);
        cpa16(aH + ar1 * 80 + ao1 * 16, Ah + (size_t)(m0 + ar1) * DMOD + k0 + ao1 * 8);
        cpa16(aL + ar0 * 80 + ao0 * 16, Al + (size_t)(m0 + ar0) * DMOD + k0 + ao0 * 8);
        cpa16(aL + ar1 * 80 + ao1 * 16, Al + (size_t)(m0 + ar1) * DMOD + k0 + ao1 * 8);
        cpa16(bH + br * 80 + bo * 16,   Wh + (size_t)(n0 + br) * DMOD + k0 + bo * 8);
        cpa16(bL + br * 80 + bo * 16,   Wl + (size_t)(n0 + br) * DMOD + k0 + bo * 8);
        asm volatile("cp.async.commit_group;\n" ::);
    };

    const uint32_t lmOff = (uint32_t)((lane & 15) * 80 + (lane >> 4) * 16);

    float acc[2][4][4];
#pragma unroll
    for (int mt = 0; mt < 2; mt++)
#pragma unroll
        for (int nt = 0; nt < 4; nt++)
#pragma unroll
            for (int i = 0; i < 4; i++) acc[mt][nt][i] = 0.f;

    issue(0, 0);
    issue(1, 1);

    for (int kc = 0; kc < 32; kc++) {
        if (kc < 31) cp_wait<1>(); else cp_wait<0>();
        __syncthreads();

        const int stg = kc & 1;
        const uint32_t aHB = smB + stg * STG_B;
        const uint32_t aLB = aHB + SA_B;
        const uint32_t bHB = aLB + SA_B;
        const uint32_t bLB = bHB + SB_B;

#pragma unroll
        for (int s = 0; s < 2; s++) {
            const uint32_t sB = (uint32_t)(s * 32) + lmOff;

            uint32_t ah[2][4], al[2][4], bh[4][2], bl[4][2];
#pragma unroll
            for (int mt = 0; mt < 2; mt++) {
                uint32_t ro = (uint32_t)((wr * 32 + mt * 16) * 80);
                ldsm_x4(ah[mt], aHB + ro + sB);
                ldsm_x4(al[mt], aLB + ro + sB);
            }
#pragma unroll
            for (int ntp = 0; ntp < 2; ntp++) {
                uint32_t ro = (uint32_t)((wc * 32 + ntp * 16) * 80);
                uint32_t b4[4];
                ldsm_x4(b4, bHB + ro + sB);
                bh[2 * ntp][0] = b4[0];     bh[2 * ntp][1] = b4[2];
                bh[2 * ntp + 1][0] = b4[1]; bh[2 * ntp + 1][1] = b4[3];
                ldsm_x4(b4, bLB + ro + sB);
                bl[2 * ntp][0] = b4[0];     bl[2 * ntp][1] = b4[2];
                bl[2 * ntp + 1][0] = b4[1]; bl[2 * ntp + 1][1] = b4[3];
            }
#pragma unroll
            for (int mt = 0; mt < 2; mt++)
#pragma unroll
                for (int nt = 0; nt < 4; nt++) {
                    mma16816(acc[mt][nt], al[mt], bh[nt]);
                    mma16816(acc[mt][nt], ah[mt], bl[nt]);
                    mma16816(acc[mt][nt], ah[mt], bh[nt]);
                }
        }
        __syncthreads();
        if (kc + 2 < 32) issue(kc + 2, stg);
    }

    // ------------------------------- epilogue -------------------------------
#pragma unroll
    for (int mt = 0; mt < 2; mt++) {
#pragma unroll
        for (int rh = 0; rh < 2; rh++) {
            int m  = m0 + wr * 32 + mt * 16 + g + rh * 8;
            int bb = m >> 11;
            int ss = m & (SEQ - 1);
#pragma unroll
            for (int nt = 0; nt < 4; nt++) {
                float c0 = acc[mt][nt][rh * 2 + 0];
                float c1 = acc[mt][nt][rh * 2 + 1];
                int n = n0 + wc * 32 + nt * 8 + t * 2;
                if (mode == 3) {
                    *(float2*)&out[(size_t)m * DMOD + n] = make_float2(c0, c1);
                } else {
                    int h = n >> 6, i0 = n & 63;
                    size_t idx = (((size_t)(bb * NH + h)) * SEQ + ss) * DK + i0;
                    uint32_t hi, lo;
                    if (mode == 2) {
                        split2(c0, c1, hi, lo);
                        *(uint32_t*)&g_Vh[idx] = hi;
                        *(uint32_t*)&g_Vl[idx] = lo;
                    } else {
                        float2 cssn = g_cs[ss][i0 >> 1];
                        float r0 = c0 * cssn.x - c1 * cssn.y;
                        float r1 = c1 * cssn.x + c0 * cssn.y;
                        split2(r0, r1, hi, lo);
                        if (mode == 0) {
                            *(uint32_t*)&g_Qh[idx] = hi;
                            *(uint32_t*)&g_Ql[idx] = lo;
                        } else {
                            *(uint32_t*)&g_Kh[idx] = hi;
                            *(uint32_t*)&g_Kl[idx] = lo;
                        }
                    }
                }
            }
        }
    }
}

// ---------------------------------------------------------------------------
// MMA flash attention (3xBF16 split), causal.  PRE-SPLIT Q/K/V inputs,
// cp.async DOUBLE-BUFFERED K/V stages, ldmatrix.x4 fragment loads.
// CTA: 64 queries, 4 warps. grid=(SEQ/64, B*NH), block=128.
// ---------------------------------------------------------------------------
#define TPITCH  144                    // bytes per smem row (72 bf16)
#define TILE_B  (64*TPITCH)            // 9216 B per tile
#define STAGE_B (4*TILE_B)             // 36864 B per stage (Kh|Kl|Vh|Vl)
#define ASM_TOT (2*STAGE_B)            // 73728 B

__global__ __launch_bounds__(128) void attn_mma_kernel()
{
    extern __shared__ char smem[];
    const uint32_t smemB = (uint32_t)__cvta_generic_to_shared(smem);

    const int tid  = threadIdx.x;
    const int w    = tid >> 5;
    const int lane = tid & 31;
    const int g = lane >> 2, t = lane & 3;
    const int qt = (int)gridDim.x - 1 - (int)blockIdx.x;   // heavy blocks first
    const int bh = blockIdx.y;
    const int q0 = qt * 64;

    const size_t hb = (size_t)bh * SEQ * DK;
    const __nv_bfloat16* kv_src[4] = {g_Kh + hb, g_Kl + hb, g_Vh + hb, g_Vl + hb};

    // --- Q fragments: direct packed-pair loads from pre-split Q ---
    uint32_t qh[4][4], ql[4][4];
    {
        const __nv_bfloat16* qh0 = g_Qh + hb + (size_t)(q0 + w * 16 + g) * DK;
        const __nv_bfloat16* ql0 = g_Ql + hb + (size_t)(q0 + w * 16 + g) * DK;
#pragma unroll
        for (int ks = 0; ks < 4; ks++) {
            int c = ks * 16 + 2 * t;
            qh[ks][0] = *(const uint32_t*)&qh0[c];
            qh[ks][1] = *(const uint32_t*)&qh0[8 * DK + c];
            qh[ks][2] = *(const uint32_t*)&qh0[c + 8];
            qh[ks][3] = *(const uint32_t*)&qh0[8 * DK + c + 8];
            ql[ks][0] = *(const uint32_t*)&ql0[c];
            ql[ks][1] = *(const uint32_t*)&ql0[8 * DK + c];
            ql[ks][2] = *(const uint32_t*)&ql0[c + 8];
            ql[ks][3] = *(const uint32_t*)&ql0[8 * DK + c + 8];
        }
    }

    // ldmatrix.x4 per-lane partial offsets (R8-verified)
    const uint32_t kPart = (uint32_t)((lane & 7) * TPITCH + (lane >> 3) * 16);
    const uint32_t vPart = (uint32_t)(((lane & 7) + 8 * ((lane >> 3) & 1)) * TPITCH
                                      + (lane >> 4) * 16);

    auto issue = [&](int kt, int stg) {
        uint32_t base = smemB + stg * STAGE_B;
#pragma unroll
        for (int a = 0; a < 4; a++) {
            const __nv_bfloat16* s = kv_src[a] + (size_t)kt * 64 * DK;
#pragma unroll
            for (int i = 0; i < 4; i++) {
                int c = tid + i * 128;                  // 0..511
                cpa16(base + a * TILE_B + (c >> 3) * TPITCH + (c & 7) * 16,
                      s + (size_t)(c >> 3) * DK + (c & 7) * 8);
            }
        }
        asm volatile("cp.async.commit_group;\n" ::);
    };

    float oacc[8][4];
#pragma unroll
    for (int nt = 0; nt < 8; nt++)
#pragma unroll
        for (int i = 0; i < 4; i++) oacc[nt][i] = 0.f;
    float mrow[2] = {-1e30f, -1e30f};
    float lrow[2] = {0.f, 0.f};

    issue(0, 0);

    for (int kt = 0; kt <= qt; kt++) {
        const int stg = kt & 1;
        if (kt < qt) { issue(kt + 1, stg ^ 1); cp_wait<1>(); }
        else         { cp_wait<0>(); }
        __syncthreads();

        const uint32_t khB = smemB + stg * STAGE_B;
        const uint32_t klB = khB + TILE_B;
        const uint32_t vhB = khB + 2 * TILE_B;
        const uint32_t vlB = khB + 3 * TILE_B;

        // --- S = Q K^T (x4 loads: matrices {0,1},{2,3} = k16-chunks) ---
        float sacc[8][4];
#pragma unroll
        for (int nt = 0; nt < 8; nt++) {
#pragma unroll
            for (int i = 0; i < 4; i++) sacc[nt][i] = 0.f;
#pragma unroll
            for (int ks2 = 0; ks2 < 2; ks2++) {
                uint32_t bh4[4], bl4[4];
                uint32_t off = (uint32_t)(nt * 8 * TPITCH + ks2 * 64) + kPart;
                ldsm_x4(bh4, khB + off);
                ldsm_x4(bl4, klB + off);
                mma16816(sacc[nt], ql[2 * ks2],     bh4 + 0);
                mma16816(sacc[nt], qh[2 * ks2],     bl4 + 0);
                mma16816(sacc[nt], qh[2 * ks2],     bh4 + 0);
                mma16816(sacc[nt], ql[2 * ks2 + 1], bh4 + 2);
                mma16816(sacc[nt], qh[2 * ks2 + 1], bl4 + 2);
                mma16816(sacc[nt], qh[2 * ks2 + 1], bh4 + 2);
            }
        }

#pragma unroll
        for (int nt = 0; nt < 8; nt++)
#pragma unroll
            for (int i = 0; i < 4; i++) sacc[nt][i] *= 0.125f;
        if (kt == qt) {
#pragma unroll
            for (int nt = 0; nt < 8; nt++)
#pragma unroll
                for (int i = 0; i < 4; i++) {
                    int col = nt * 8 + 2 * t + (i & 1);
                    int row = w * 16 + g + 8 * (i >> 1);
                    if (col > row) sacc[nt][i] = -1e30f;
                }
        }

        // --- online softmax ---
#pragma unroll
        for (int r = 0; r < 2; r++) {
            float mx = -1e30f;
#pragma unroll
            for (int nt = 0; nt < 8; nt++) {
                mx = fmaxf(mx, sacc[nt][2 * r]);
                mx = fmaxf(mx, sacc[nt][2 * r + 1]);
            }
            mx = fmaxf(mx, __shfl_xor_sync(0xffffffffu, mx, 1));
            mx = fmaxf(mx, __shfl_xor_sync(0xffffffffu, mx, 2));
            float mnew = fmaxf(mrow[r], mx);
            float corr = __expf(mrow[r] - mnew);
            mrow[r] = mnew;
            float rs = 0.f;
#pragma unroll
            for (int nt = 0; nt < 8; nt++) {
                float p0 = __expf(sacc[nt][2 * r]     - mnew);
                float p1 = __expf(sacc[nt][2 * r + 1] - mnew);
                sacc[nt][2 * r] = p0; sacc[nt][2 * r + 1] = p1;
                rs += p0 + p1;
            }
            rs += __shfl_xor_sync(0xffffffffu, rs, 1);
            rs += __shfl_xor_sync(0xffffffffu, rs, 2);
            lrow[r] = lrow[r] * corr + rs;
#pragma unroll
            for (int nt = 0; nt < 8; nt++) {
                oacc[nt][2 * r]     *= corr;
                oacc[nt][2 * r + 1] *= corr;
            }
        }

        // --- O += P V (x4 trans loads: two nt per instruction) ---
#pragma unroll
        for (int kc = 0; kc < 4; kc++) {
            uint32_t pah[4], pal[4];
            split2(sacc[2 * kc][0],     sacc[2 * kc][1],     pah[0], pal[0]);
            split2(sacc[2 * kc][2],     sacc[2 * kc][3],     pah[1], pal[1]);
            split2(sacc[2 * kc + 1][0], sacc[2 * kc + 1][1], pah[2], pal[2]);
            split2(sacc[2 * kc + 1][2], sacc[2 * kc + 1][3], pah[3], pal[3]);
#pragma unroll
            for (int nt2 = 0; nt2 < 4; nt2++) {
                uint32_t vh4[4], vl4[4];
                uint32_t off = (uint32_t)(kc * 16 * TPITCH + nt2 * 32) + vPart;
                ldsm_x4_t(vh4, vhB + off);
                ldsm_x4_t(vl4, vlB + off);
                mma16816(oacc[2 * nt2],     pah, vh4 + 0);
                mma16816(oacc[2 * nt2],     pah, vl4 + 0);
                mma16816(oacc[2 * nt2],     pal, vh4 + 0);
                mma16816(oacc[2 * nt2 + 1], pah, vh4 + 2);
                mma16816(oacc[2 * nt2 + 1], pah, vl4 + 2);
                mma16816(oacc[2 * nt2 + 1], pal, vh4 + 2);
            }
        }
        __syncthreads();
    }

    // epilogue: write SPLIT O (bf16 hi/lo) for the pre-split Wo GEMM
    const int bb = bh >> 4;
    const int h  = bh & 15;
#pragma unroll
    for (int r = 0; r < 2; r++) {
        float inv = 1.f / lrow[r];
        int q = q0 + w * 16 + g + 8 * r;
        size_t rowoff = ((size_t)(bb * SEQ + q)) * DMOD + h * DK;
#pragma unroll
        for (int nt = 0; nt < 8; nt++) {
            uint32_t hi, lo;
            split2(oacc[nt][2 * r] * inv, oacc[nt][2 * r + 1] * inv, hi, lo);
            *(uint32_t*)&g_Oh[rowoff + nt * 8 + 2 * t] = hi;
            *(uint32_t*)&g_Ol[rowoff + nt * 8 + 2 * t] = lo;
        }
    }
}

// ---------------------------------------------------------------------------
extern "C" void kernel_launch(void* const* d_in, const int* in_sizes, int n_in,
                              void* d_out, int out_size)
{
    const float* X  = (const float*)d_in[0];
    const float* Wq = (const float*)d_in[1];
    const float* Wk = (const float*)d_in[2];
    const float* Wv = (const float*)d_in[3];
    const float* Wo = (const float*)d_in[4];
    float* out = (float*)d_out;

    prep_kernel<<<8448, 256>>>(X, Wq, Wk, Wv, Wo);

    cudaFuncSetAttribute(gemm_mma_kernel,
                         cudaFuncAttributeMaxDynamicSharedMemorySize, GSM_TOT);
    cudaFuncSetAttribute(attn_mma_kernel,
                         cudaFuncAttributeMaxDynamicSharedMemorySize, ASM_TOT);

    // fused QKV: grid.x = 3 modes * 16 n-tiles
    gemm_mma_kernel<<<dim3(48, MROWS / 128), 256, GSM_TOT>>>(nullptr, -1);

    attn_mma_kernel<<<dim3(SEQ / 64, BATCH * NH), 128, ASM_TOT>>>();

    gemm_mma_kernel<<<dim3(16, MROWS / 128), 256, GSM_TOT>>>(out, 3);
}

// round 16
// speedup vs baseline: 1.5966x; 1.0109x over previous
#include <cuda_runtime.h>
#include <cuda_bf16.h>
#include <math.h>
#include <stdint.h>

// Problem constants
#define BATCH 2
#define SEQ   2048
#define DMOD  1024
#define NH    16
#define DK    64
#define MROWS (BATCH*SEQ)   // 4096

// ------------------------- global scratch (no allocs) -----------------------
__device__ __nv_bfloat16 g_Xh[MROWS*DMOD],  g_Xl[MROWS*DMOD];
__device__ __nv_bfloat16 g_Wh[4*DMOD*DMOD], g_Wl[4*DMOD*DMOD];
__device__ __nv_bfloat16 g_Qh[BATCH*NH*SEQ*DK], g_Ql[BATCH*NH*SEQ*DK];
__device__ __nv_bfloat16 g_Kh[BATCH*NH*SEQ*DK], g_Kl[BATCH*NH*SEQ*DK];
__device__ __nv_bfloat16 g_Vh[BATCH*NH*SEQ*DK], g_Vl[BATCH*NH*SEQ*DK];
__device__ __nv_bfloat16 g_Oh[MROWS*DMOD],  g_Ol[MROWS*DMOD];
__device__ float2 g_cs[SEQ][DK/2];       // (cos, sin) per (pos, pair)

// ------------------------------- helpers ------------------------------------
__device__ __forceinline__ void split2(float e, float o, uint32_t& hi, uint32_t& lo)
{
    __nv_bfloat16 eh = __float2bfloat16(e);
    __nv_bfloat16 oh = __float2bfloat16(o);
    float er  = e - __bfloat162float(eh);
    float orr = o - __bfloat162float(oh);
    __nv_bfloat16 el = __float2bfloat16(er);
    __nv_bfloat16 ol = __float2bfloat16(orr);
    hi = (uint32_t)__bfloat16_as_ushort(eh) | ((uint32_t)__bfloat16_as_ushort(oh) << 16);
    lo = (uint32_t)__bfloat16_as_ushort(el) | ((uint32_t)__bfloat16_as_ushort(ol) << 16);
}

__device__ __forceinline__ void mma16816(float* c, const uint32_t* a, const uint32_t* b)
{
    asm volatile(
        "mma.sync.aligned.m16n8k16.row.col.f32.bf16.bf16.f32 "
        "{%0,%1,%2,%3}, {%4,%5,%6,%7}, {%8,%9}, {%0,%1,%2,%3};\n"
        : "+f"(c[0]), "+f"(c[1]), "+f"(c[2]), "+f"(c[3])
        : "r"(a[0]), "r"(a[1]), "r"(a[2]), "r"(a[3]), "r"(b[0]), "r"(b[1]));
}
__device__ __forceinline__ void ldsm_x4(uint32_t* r, uint32_t addr)
{
    asm volatile("ldmatrix.sync.aligned.m8n8.x4.shared.b16 {%0,%1,%2,%3}, [%4];"
                 : "=r"(r[0]), "=r"(r[1]), "=r"(r[2]), "=r"(r[3]) : "r"(addr));
}
__device__ __forceinline__ void ldsm_x4_t(uint32_t* r, uint32_t addr)
{
    asm volatile("ldmatrix.sync.aligned.m8n8.x4.trans.shared.b16 {%0,%1,%2,%3}, [%4];"
                 : "=r"(r[0]), "=r"(r[1]), "=r"(r[2]), "=r"(r[3]) : "r"(addr));
}
__device__ __forceinline__ void cpa16(uint32_t dst, const void* src)
{
    asm volatile("cp.async.cg.shared.global [%0], [%1], 16;" :: "r"(dst), "l"(src));
}
template<int N> __device__ __forceinline__ void cp_wait()
{
    asm volatile("cp.async.wait_group %0;" :: "n"(N) : "memory");
}

// -------------------- fused prep kernel (splits + rope) ----------------------
// blocks [0,4096): split X      blocks [4096,8192): split W (1024 per matrix)
// blocks [8192,8448): rope table
__global__ void prep_kernel(const float* __restrict__ X,
                            const float* __restrict__ Wq,
                            const float* __restrict__ Wk,
                            const float* __restrict__ Wv,
                            const float* __restrict__ Wo)
{
    const int b = blockIdx.x;
    if (b < 8192) {
        const float* src;
        __nv_bfloat16 *h, *l;
        int i;
        if (b < 4096) {                                   // X: 4096 blocks
            src = X; h = g_Xh; l = g_Xl;
            i = (b << 8) + threadIdx.x;
        } else {                                          // W: 1024 blocks each
            const int wb  = b - 4096;
            const int sel = wb >> 10;                     // 0..3
            src = (sel == 0) ? Wq : (sel == 1) ? Wk : (sel == 2) ? Wv : Wo;
            h = g_Wh + (size_t)sel * DMOD * DMOD;
            l = g_Wl + (size_t)sel * DMOD * DMOD;
            i = ((wb & 1023) << 8) + threadIdx.x;
        }
        float4 v = ((const float4*)src)[i];
        uint32_t h0, l0, h1, l1;
        split2(v.x, v.y, h0, l0);
        split2(v.z, v.w, h1, l1);
        *(uint32_t*)&h[4 * i]     = h0;
        *(uint32_t*)&h[4 * i + 2] = h1;
        *(uint32_t*)&l[4 * i]     = l0;
        *(uint32_t*)&l[4 * i + 2] = l1;
    } else {
        int idx = ((b - 8192) << 8) + threadIdx.x;        // SEQ*32
        int s = idx >> 5, j = idx & 31;
        float invf = powf(10000.0f, -(float)(2 * j) / 64.0f);
        float ang = (float)s * invf;
        float sn, cs;
        sincosf(ang, &sn, &cs);
        g_cs[s][j] = make_float2(cs, sn);
    }
}

// ---------------------------------------------------------------------------
// Tensor-core GEMM (3xBF16 split, PRE-SPLIT inputs, cp.async double-buffered).
// Now forced to 3 CTAs/SM via launch_bounds (regs capped at 80).
// ---------------------------------------------------------------------------
#define APITCH   40
#define SA_B     (128*APITCH*2)            // 10240
#define SB_B     (64*APITCH*2)             // 5120
#define STG_B    (2*SA_B + 2*SB_B)         // 30720
#define GSM_TOT  (2*STG_B)                 // 61440

__global__ __launch_bounds__(256, 3) void gemm_mma_kernel(
    float* __restrict__ out, int mode_in)
{
    extern __shared__ char sm[];
    const uint32_t smB = (uint32_t)__cvta_generic_to_shared(sm);

    int mode, n0;
    if (mode_in < 0) { mode = (int)blockIdx.x >> 4; n0 = ((int)blockIdx.x & 15) * 64; }
    else             { mode = 3;                    n0 = (int)blockIdx.x * 64; }
    const int m0 = (int)blockIdx.y * 128;

    const __nv_bfloat16* Ah = (mode == 3) ? g_Oh : g_Xh;
    const __nv_bfloat16* Al = (mode == 3) ? g_Ol : g_Xl;
    const __nv_bfloat16* Wh = g_Wh + (size_t)mode * DMOD * DMOD;
    const __nv_bfloat16* Wl = g_Wl + (size_t)mode * DMOD * DMOD;

    const int tid  = threadIdx.x;
    const int warp = tid >> 5, lane = tid & 31;
    const int wr = warp >> 1, wc = warp & 1;
    const int g = lane >> 2, t = lane & 3;

    const int ar0 = tid >> 2,         ao0 = tid & 3;
    const int ar1 = (tid + 256) >> 2, ao1 = (tid + 256) & 3;
    const int br  = tid >> 2,         bo  = tid & 3;

    auto issue = [&](int kc, int stg) {
        const int k0 = kc * 32;
        const uint32_t aH = smB + stg * STG_B;
        const uint32_t aL = aH + SA_B;
        const uint32_t bH = aL + SA_B;
        const uint32_t bL = bH + SB_B;
        cpa16(aH + ar0 * 80 + ao0 * 16, Ah + (size_t)(m0 + ar0) * DMOD + k0 + ao0 * 8);
        cpa16(aH + ar1 * 80 + ao1 * 16, Ah + (size_t)(m0 + ar1) * DMOD + k0 + ao1 * 8);
        cpa16(aL + ar0 * 80 + ao0 * 16, Al + (size_t)(m0 + ar0) * DMOD + k0 + ao0 * 8);
        cpa16(aL + ar1 * 80 + ao1 * 16, Al + (size_t)(m0 + ar1) * DMOD + k0 + ao1 * 8);
        cpa16(bH + br * 80 + bo * 16,   Wh + (size_t)(n0 + br) * DMOD + k0 + bo * 8);
        cpa16(bL + br * 80 + bo * 16,   Wl + (size_t)(n0 + br) * DMOD + k0 + bo * 8);
        asm volatile("cp.async.commit_group;\n" ::);
    };

    const uint32_t lmOff = (uint32_t)((lane & 15) * 80 + (lane >> 4) * 16);

    float acc[2][4][4];
#pragma unroll
    for (int mt = 0; mt < 2; mt++)
#pragma unroll
        for (int nt = 0; nt < 4; nt++)
#pragma unroll
            for (int i = 0; i < 4; i++) acc[mt][nt][i] = 0.f;

    issue(0, 0);
    issue(1, 1);

    for (int kc = 0; kc < 32; kc++) {
        if (kc < 31) cp_wait<1>(); else cp_wait<0>();
        __syncthreads();

        const int stg = kc & 1;
        const uint32_t aHB = smB + stg * STG_B;
        const uint32_t aLB = aHB + SA_B;
        const uint32_t bHB = aLB + SA_B;
        const uint32_t bLB = bHB + SB_B;

#pragma unroll
        for (int s = 0; s < 2; s++) {
            const uint32_t sB = (uint32_t)(s * 32) + lmOff;

            uint32_t ah[2][4], al[2][4], bh[4][2], bl[4][2];
#pragma unroll
            for (int mt = 0; mt < 2; mt++) {
                uint32_t ro = (uint32_t)((wr * 32 + mt * 16) * 80);
                ldsm_x4(ah[mt], aHB + ro + sB);
                ldsm_x4(al[mt], aLB + ro + sB);
            }
#pragma unroll
            for (int ntp = 0; ntp < 2; ntp++) {
                uint32_t ro = (uint32_t)((wc * 32 + ntp * 16) * 80);
                uint32_t b4[4];
                ldsm_x4(b4, bHB + ro + sB);
                bh[2 * ntp][0] = b4[0];     bh[2 * ntp][1] = b4[2];
                bh[2 * ntp + 1][0] = b4[1]; bh[2 * ntp + 1][1] = b4[3];
                ldsm_x4(b4, bLB + ro + sB);
                bl[2 * ntp][0] = b4[0];     bl[2 * ntp][1] = b4[2];
                bl[2 * ntp + 1][0] = b4[1]; bl[2 * ntp + 1][1] = b4[3];
            }
#pragma unroll
            for (int mt = 0; mt < 2; mt++)
#pragma unroll
                for (int nt = 0; nt < 4; nt++) {
                    mma16816(acc[mt][nt], al[mt], bh[nt]);
                    mma16816(acc[mt][nt], ah[mt], bl[nt]);
                    mma16816(acc[mt][nt], ah[mt], bh[nt]);
                }
        }
        __syncthreads();
        if (kc + 2 < 32) issue(kc + 2, stg);
    }

    // ------------------------------- epilogue -------------------------------
#pragma unroll
    for (int mt = 0; mt < 2; mt++) {
#pragma unroll
        for (int rh = 0; rh < 2; rh++) {
            int m  = m0 + wr * 32 + mt * 16 + g + rh * 8;
            int bb = m >> 11;
            int ss = m & (SEQ - 1);
#pragma unroll
            for (int nt = 0; nt < 4; nt++) {
                float c0 = acc[mt][nt][rh * 2 + 0];
                float c1 = acc[mt][nt][rh * 2 + 1];
                int n = n0 + wc * 32 + nt * 8 + t * 2;
                if (mode == 3) {
                    *(float2*)&out[(size_t)m * DMOD + n] = make_float2(c0, c1);
                } else {
                    int h = n >> 6, i0 = n & 63;
                    size_t idx = (((size_t)(bb * NH + h)) * SEQ + ss) * DK + i0;
                    uint32_t hi, lo;
                    if (mode == 2) {
                        split2(c0, c1, hi, lo);
                        *(uint32_t*)&g_Vh[idx] = hi;
                        *(uint32_t*)&g_Vl[idx] = lo;
                    } else {
                        float2 cssn = g_cs[ss][i0 >> 1];
                        float r0 = c0 * cssn.x - c1 * cssn.y;
                        float r1 = c1 * cssn.x + c0 * cssn.y;
                        split2(r0, r1, hi, lo);
                        if (mode == 0) {
                            *(uint32_t*)&g_Qh[idx] = hi;
                            *(uint32_t*)&g_Ql[idx] = lo;
                        } else {
                            *(uint32_t*)&g_Kh[idx] = hi;
                            *(uint32_t*)&g_Kl[idx] = lo;
                        }
                    }
                }
            }
        }
    }
}

// ---------------------------------------------------------------------------
// MMA flash attention (3xBF16 split), causal.  PRE-SPLIT Q/K/V inputs,
// cp.async double-buffered, ldmatrix.x4.  Forced toward 3 CTAs/SM.
// ---------------------------------------------------------------------------
#define TPITCH  144                    // bytes per smem row (72 bf16)
#define TILE_B  (64*TPITCH)            // 9216 B per tile
#define STAGE_B (4*TILE_B)             // 36864 B per stage (Kh|Kl|Vh|Vl)
#define ASM_TOT (2*STAGE_B)            // 73728 B

__global__ __launch_bounds__(128, 3) void attn_mma_kernel()
{
    extern __shared__ char smem[];
    const uint32_t smemB = (uint32_t)__cvta_generic_to_shared(smem);

    const int tid  = threadIdx.x;
    const int w    = tid >> 5;
    const int lane = tid & 31;
    const int g = lane >> 2, t = lane & 3;
    const int qt = (int)gridDim.x - 1 - (int)blockIdx.x;   // heavy blocks first
    const int bh = blockIdx.y;
    const int q0 = qt * 64;

    const size_t hb = (size_t)bh * SEQ * DK;
    const __nv_bfloat16* kv_src[4] = {g_Kh + hb, g_Kl + hb, g_Vh + hb, g_Vl + hb};

    // --- Q fragments: direct packed-pair loads from pre-split Q ---
    uint32_t qh[4][4], ql[4][4];
    {
        const __nv_bfloat16* qh0 = g_Qh + hb + (size_t)(q0 + w * 16 + g) * DK;
        const __nv_bfloat16* ql0 = g_Ql + hb + (size_t)(q0 + w * 16 + g) * DK;
#pragma unroll
        for (int ks = 0; ks < 4; ks++) {
            int c = ks * 16 + 2 * t;
            qh[ks][0] = *(const uint32_t*)&qh0[c];
            qh[ks][1] = *(const uint32_t*)&qh0[8 * DK + c];
            qh[ks][2] = *(const uint32_t*)&qh0[c + 8];
            qh[ks][3] = *(const uint32_t*)&qh0[8 * DK + c + 8];
            ql[ks][0] = *(const uint32_t*)&ql0[c];
            ql[ks][1] = *(const uint32_t*)&ql0[8 * DK + c];
            ql[ks][2] = *(const uint32_t*)&ql0[c + 8];
            ql[ks][3] = *(const uint32_t*)&ql0[8 * DK + c + 8];
        }
    }

    const uint32_t kPart = (uint32_t)((lane & 7) * TPITCH + (lane >> 3) * 16);
    const uint32_t vPart = (uint32_t)(((lane & 7) + 8 * ((lane >> 3) & 1)) * TPITCH
                                      + (lane >> 4) * 16);

    auto issue = [&](int kt, int stg) {
        uint32_t base = smemB + stg * STAGE_B;
#pragma unroll
        for (int a = 0; a < 4; a++) {
            const __nv_bfloat16* s = kv_src[a] + (size_t)kt * 64 * DK;
#pragma unroll
            for (int i = 0; i < 4; i++) {
                int c = tid + i * 128;                  // 0..511
                cpa16(base + a * TILE_B + (c >> 3) * TPITCH + (c & 7) * 16,
                      s + (size_t)(c >> 3) * DK + (c & 7) * 8);
            }
        }
        asm volatile("cp.async.commit_group;\n" ::);
    };

    float oacc[8][4];
#pragma unroll
    for (int nt = 0; nt < 8; nt++)
#pragma unroll
        for (int i = 0; i < 4; i++) oacc[nt][i] = 0.f;
    float mrow[2] = {-1e30f, -1e30f};
    float lrow[2] = {0.f, 0.f};

    issue(0, 0);

    for (int kt = 0; kt <= qt; kt++) {
        const int stg = kt & 1;
        if (kt < qt) { issue(kt + 1, stg ^ 1); cp_wait<1>(); }
        else         { cp_wait<0>(); }
        __syncthreads();

        const uint32_t khB = smemB + stg * STAGE_B;
        const uint32_t klB = khB + TILE_B;
        const uint32_t vhB = khB + 2 * TILE_B;
        const uint32_t vlB = khB + 3 * TILE_B;

        // --- S = Q K^T ---
        float sacc[8][4];
#pragma unroll
        for (int nt = 0; nt < 8; nt++) {
#pragma unroll
            for (int i = 0; i < 4; i++) sacc[nt][i] = 0.f;
#pragma unroll
            for (int ks2 = 0; ks2 < 2; ks2++) {
                uint32_t bh4[4], bl4[4];
                uint32_t off = (uint32_t)(nt * 8 * TPITCH + ks2 * 64) + kPart;
                ldsm_x4(bh4, khB + off);
                ldsm_x4(bl4, klB + off);
                mma16816(sacc[nt], ql[2 * ks2],     bh4 + 0);
                mma16816(sacc[nt], qh[2 * ks2],     bl4 + 0);
                mma16816(sacc[nt], qh[2 * ks2],     bh4 + 0);
                mma16816(sacc[nt], ql[2 * ks2 + 1], bh4 + 2);
                mma16816(sacc[nt], qh[2 * ks2 + 1], bl4 + 2);
                mma16816(sacc[nt], qh[2 * ks2 + 1], bh4 + 2);
            }
        }

#pragma unroll
        for (int nt = 0; nt < 8; nt++)
#pragma unroll
            for (int i = 0; i < 4; i++) sacc[nt][i] *= 0.125f;
        if (kt == qt) {
#pragma unroll
            for (int nt = 0; nt < 8; nt++)
#pragma unroll
                for (int i = 0; i < 4; i++) {
                    int col = nt * 8 + 2 * t + (i & 1);
                    int row = w * 16 + g + 8 * (i >> 1);
                    if (col > row) sacc[nt][i] = -1e30f;
                }
        }

        // --- online softmax ---
#pragma unroll
        for (int r = 0; r < 2; r++) {
            float mx = -1e30f;
#pragma unroll
            for (int nt = 0; nt < 8; nt++) {
                mx = fmaxf(mx, sacc[nt][2 * r]);
                mx = fmaxf(mx, sacc[nt][2 * r + 1]);
            }
            mx = fmaxf(mx, __shfl_xor_sync(0xffffffffu, mx, 1));
            mx = fmaxf(mx, __shfl_xor_sync(0xffffffffu, mx, 2));
            float mnew = fmaxf(mrow[r], mx);
            float corr = __expf(mrow[r] - mnew);
            mrow[r] = mnew;
            float rs = 0.f;
#pragma unroll
            for (int nt = 0; nt < 8; nt++) {
                float p0 = __expf(sacc[nt][2 * r]     - mnew);
                float p1 = __expf(sacc[nt][2 * r + 1] - mnew);
                sacc[nt][2 * r] = p0; sacc[nt][2 * r + 1] = p1;
                rs += p0 + p1;
            }
            rs += __shfl_xor_sync(0xffffffffu, rs, 1);
            rs += __shfl_xor_sync(0xffffffffu, rs, 2);
            lrow[r] = lrow[r] * corr + rs;
#pragma unroll
            for (int nt = 0; nt < 8; nt++) {
                oacc[nt][2 * r]     *= corr;
                oacc[nt][2 * r + 1] *= corr;
            }
        }

        // --- O += P V ---
#pragma unroll
        for (int kc = 0; kc < 4; kc++) {
            uint32_t pah[4], pal[4];
            split2(sacc[2 * kc][0],     sacc[2 * kc][1],     pah[0], pal[0]);
            split2(sacc[2 * kc][2],     sacc[2 * kc][3],     pah[1], pal[1]);
            split2(sacc[2 * kc + 1][0], sacc[2 * kc + 1][1], pah[2], pal[2]);
            split2(sacc[2 * kc + 1][2], sacc[2 * kc + 1][3], pah[3], pal[3]);
#pragma unroll
            for (int nt2 = 0; nt2 < 4; nt2++) {
                uint32_t vh4[4], vl4[4];
                uint32_t off = (uint32_t)(kc * 16 * TPITCH + nt2 * 32) + vPart;
                ldsm_x4_t(vh4, vhB + off);
                ldsm_x4_t(vl4, vlB + off);
                mma16816(oacc[2 * nt2],     pah, vh4 + 0);
                mma16816(oacc[2 * nt2],     pah, vl4 + 0);
                mma16816(oacc[2 * nt2],     pal, vh4 + 0);
                mma16816(oacc[2 * nt2 + 1], pah, vh4 + 2);
                mma16816(oacc[2 * nt2 + 1], pah, vl4 + 2);
                mma16816(oacc[2 * nt2 + 1], pal, vh4 + 2);
            }
        }
        __syncthreads();
    }

    // epilogue: write SPLIT O (bf16 hi/lo) for the pre-split Wo GEMM
    const int bb = bh >> 4;
    const int h  = bh & 15;
#pragma unroll
    for (int r = 0; r < 2; r++) {
        float inv = 1.f / lrow[r];
        int q = q0 + w * 16 + g + 8 * r;
        size_t rowoff = ((size_t)(bb * SEQ + q)) * DMOD + h * DK;
#pragma unroll
        for (int nt = 0; nt < 8; nt++) {
            uint32_t hi, lo;
            split2(oacc[nt][2 * r] * inv, oacc[nt][2 * r + 1] * inv, hi, lo);
            *(uint32_t*)&g_Oh[rowoff + nt * 8 + 2 * t] = hi;
            *(uint32_t*)&g_Ol[rowoff + nt * 8 + 2 * t] = lo;
        }
    }
}

// ---------------------------------------------------------------------------
extern "C" void kernel_launch(void* const* d_in, const int* in_sizes, int n_in,
                              void* d_out, int out_size)
{
    const float* X  = (const float*)d_in[0];
    const float* Wq = (const float*)d_in[1];
    const float* Wk = (const float*)d_in[2];
    const float* Wv = (const float*)d_in[3];
    const float* Wo = (const float*)d_in[4];
    float* out = (float*)d_out;

    prep_kernel<<<8448, 256>>>(X, Wq, Wk, Wv, Wo);

    cudaFuncSetAttribute(gemm_mma_kernel,
                         cudaFuncAttributeMaxDynamicSharedMemorySize, GSM_TOT);
    cudaFuncSetAttribute(attn_mma_kernel,
                         cudaFuncAttributeMaxDynamicSharedMemorySize, ASM_TOT);

    // fused QKV: grid.x = 3 modes * 16 n-tiles
    gemm_mma_kernel<<<dim3(48, MROWS / 128), 256, GSM_TOT>>>(nullptr, -1);

    attn_mma_kernel<<<dim3(SEQ / 64, BATCH * NH), 128, ASM_TOT>>>();

    gemm_mma_kernel<<<dim3(16, MROWS / 128), 256, GSM_TOT>>>(out, 3);
}

// round 17
// speedup vs baseline: 1.6737x; 1.0483x over previous
#include <cuda_runtime.h>
#include <cuda_bf16.h>
#include <math.h>
#include <stdint.h>

// Problem constants
#define BATCH 2
#define SEQ   2048
#define DMOD  1024
#define NH    16
#define DK    64
#define MROWS (BATCH*SEQ)   // 4096

// ------------------------- global scratch (no allocs) -----------------------
__device__ __nv_bfloat16 g_Xh[MROWS*DMOD],  g_Xl[MROWS*DMOD];
__device__ __nv_bfloat16 g_Wh[4*DMOD*DMOD], g_Wl[4*DMOD*DMOD];
__device__ __nv_bfloat16 g_Qh[BATCH*NH*SEQ*DK], g_Ql[BATCH*NH*SEQ*DK];
__device__ __nv_bfloat16 g_Kh[BATCH*NH*SEQ*DK], g_Kl[BATCH*NH*SEQ*DK];
__device__ __nv_bfloat16 g_Vh[BATCH*NH*SEQ*DK], g_Vl[BATCH*NH*SEQ*DK];
__device__ __nv_bfloat16 g_Oh[MROWS*DMOD],  g_Ol[MROWS*DMOD];
__device__ float2 g_cs[SEQ][DK/2];       // (cos, sin) per (pos, pair)

// ------------------------------- helpers ------------------------------------
__device__ __forceinline__ void split2(float e, float o, uint32_t& hi, uint32_t& lo)
{
    __nv_bfloat16 eh = __float2bfloat16(e);
    __nv_bfloat16 oh = __float2bfloat16(o);
    float er  = e - __bfloat162float(eh);
    float orr = o - __bfloat162float(oh);
    __nv_bfloat16 el = __float2bfloat16(er);
    __nv_bfloat16 ol = __float2bfloat16(orr);
    hi = (uint32_t)__bfloat16_as_ushort(eh) | ((uint32_t)__bfloat16_as_ushort(oh) << 16);
    lo = (uint32_t)__bfloat16_as_ushort(el) | ((uint32_t)__bfloat16_as_ushort(ol) << 16);
}

__device__ __forceinline__ void mma16816(float* c, const uint32_t* a, const uint32_t* b)
{
    asm volatile(
        "mma.sync.aligned.m16n8k16.row.col.f32.bf16.bf16.f32 "
        "{%0,%1,%2,%3}, {%4,%5,%6,%7}, {%8,%9}, {%0,%1,%2,%3};\n"
        : "+f"(c[0]), "+f"(c[1]), "+f"(c[2]), "+f"(c[3])
        : "r"(a[0]), "r"(a[1]), "r"(a[2]), "r"(a[3]), "r"(b[0]), "r"(b[1]));
}
__device__ __forceinline__ void ldsm_x4(uint32_t* r, uint32_t addr)
{
    asm volatile("ldmatrix.sync.aligned.m8n8.x4.shared.b16 {%0,%1,%2,%3}, [%4];"
                 : "=r"(r[0]), "=r"(r[1]), "=r"(r[2]), "=r"(r[3]) : "r"(addr));
}
__device__ __forceinline__ void ldsm_x4_t(uint32_t* r, uint32_t addr)
{
    asm volatile("ldmatrix.sync.aligned.m8n8.x4.trans.shared.b16 {%0,%1,%2,%3}, [%4];"
                 : "=r"(r[0]), "=r"(r[1]), "=r"(r[2]), "=r"(r[3]) : "r"(addr));
}
__device__ __forceinline__ void cpa16(uint32_t dst, const void* src)
{
    asm volatile("cp.async.cg.shared.global [%0], [%1], 16;" :: "r"(dst), "l"(src));
}
template<int N> __device__ __forceinline__ void cp_wait()
{
    asm volatile("cp.async.wait_group %0;" :: "n"(N) : "memory");
}

// -------------------- fused prep kernel (splits + rope) ----------------------
// blocks [0,4096): split X      blocks [4096,8192): split W (1024 per matrix)
// blocks [8192,8448): rope table
__global__ void prep_kernel(const float* __restrict__ X,
                            const float* __restrict__ Wq,
                            const float* __restrict__ Wk,
                            const float* __restrict__ Wv,
                            const float* __restrict__ Wo)
{
    const int b = blockIdx.x;
    if (b < 8192) {
        const float* src;
        __nv_bfloat16 *h, *l;
        int i;
        if (b < 4096) {
            src = X; h = g_Xh; l = g_Xl;
            i = (b << 8) + threadIdx.x;
        } else {
            const int wb  = b - 4096;
            const int sel = wb >> 10;
            src = (sel == 0) ? Wq : (sel == 1) ? Wk : (sel == 2) ? Wv : Wo;
            h = g_Wh + (size_t)sel * DMOD * DMOD;
            l = g_Wl + (size_t)sel * DMOD * DMOD;
            i = ((wb & 1023) << 8) + threadIdx.x;
        }
        float4 v = ((const float4*)src)[i];
        uint32_t h0, l0, h1, l1;
        split2(v.x, v.y, h0, l0);
        split2(v.z, v.w, h1, l1);
        *(uint32_t*)&h[4 * i]     = h0;
        *(uint32_t*)&h[4 * i + 2] = h1;
        *(uint32_t*)&l[4 * i]     = l0;
        *(uint32_t*)&l[4 * i + 2] = l1;
    } else {
        int idx = ((b - 8192) << 8) + threadIdx.x;
        int s = idx >> 5, j = idx & 31;
        float invf = powf(10000.0f, -(float)(2 * j) / 64.0f);
        float ang = (float)s * invf;
        float sn, cs;
        sincosf(ang, &sn, &cs);
        g_cs[s][j] = make_float2(cs, sn);
    }
}

// ---------------------------------------------------------------------------
// Tensor-core GEMM (3xBF16 split, PRE-SPLIT inputs, cp.async double-buffered).
// FAT TILE: BM=128, BN=128, BK=32. 8 warps as 2x4; warp tile 64x32 (mt=4).
// mode_in = -1: fused QKV (mode = bx>>3, n0=(bx&7)*128)   mode_in = 3: O@Wo^T
// ---------------------------------------------------------------------------
#define APITCH   40
#define SA_B     (128*APITCH*2)            // 10240 (A h or l buffer)
#define SB_B     (128*APITCH*2)            // 10240 (B h or l buffer)
#define STG_B    (2*SA_B + 2*SB_B)         // 40960
#define GSM_TOT  (2*STG_B)                 // 81920

__global__ __launch_bounds__(256, 2) void gemm_mma_kernel(
    float* __restrict__ out, int mode_in)
{
    extern __shared__ char sm[];
    const uint32_t smB = (uint32_t)__cvta_generic_to_shared(sm);

    int mode, n0;
    if (mode_in < 0) { mode = (int)blockIdx.x >> 3; n0 = ((int)blockIdx.x & 7) * 128; }
    else             { mode = 3;                    n0 = (int)blockIdx.x * 128; }
    const int m0 = (int)blockIdx.y * 128;

    const __nv_bfloat16* Ah = (mode == 3) ? g_Oh : g_Xh;
    const __nv_bfloat16* Al = (mode == 3) ? g_Ol : g_Xl;
    const __nv_bfloat16* Wh = g_Wh + (size_t)mode * DMOD * DMOD;
    const __nv_bfloat16* Wl = g_Wl + (size_t)mode * DMOD * DMOD;

    const int tid  = threadIdx.x;
    const int warp = tid >> 5, lane = tid & 31;
    const int wr = warp >> 2, wc = warp & 3;        // 2 x 4 warp grid
    const int g = lane >> 2, t = lane & 3;

    // cp.async mapping: A and B each 512 chunks of 16B -> 2/thread each (x h/l)
    const int r0 = tid >> 2,         o0 = tid & 3;
    const int r1 = (tid + 256) >> 2, o1 = (tid + 256) & 3;

    auto issue = [&](int kc, int stg) {
        const int k0 = kc * 32;
        const uint32_t aH = smB + stg * STG_B;
        const uint32_t aL = aH + SA_B;
        const uint32_t bH = aL + SA_B;
        const uint32_t bL = bH + SB_B;
        cpa16(aH + r0 * 80 + o0 * 16, Ah + (size_t)(m0 + r0) * DMOD + k0 + o0 * 8);
        cpa16(aH + r1 * 80 + o1 * 16, Ah + (size_t)(m0 + r1) * DMOD + k0 + o1 * 8);
        cpa16(aL + r0 * 80 + o0 * 16, Al + (size_t)(m0 + r0) * DMOD + k0 + o0 * 8);
        cpa16(aL + r1 * 80 + o1 * 16, Al + (size_t)(m0 + r1) * DMOD + k0 + o1 * 8);
        cpa16(bH + r0 * 80 + o0 * 16, Wh + (size_t)(n0 + r0) * DMOD + k0 + o0 * 8);
        cpa16(bH + r1 * 80 + o1 * 16, Wh + (size_t)(n0 + r1) * DMOD + k0 + o1 * 8);
        cpa16(bL + r0 * 80 + o0 * 16, Wl + (size_t)(n0 + r0) * DMOD + k0 + o0 * 8);
        cpa16(bL + r1 * 80 + o1 * 16, Wl + (size_t)(n0 + r1) * DMOD + k0 + o1 * 8);
        asm volatile("cp.async.commit_group;\n" ::);
    };

    const uint32_t lmOff = (uint32_t)((lane & 15) * 80 + (lane >> 4) * 16);

    float acc[4][4][4];
#pragma unroll
    for (int mt = 0; mt < 4; mt++)
#pragma unroll
        for (int nt = 0; nt < 4; nt++)
#pragma unroll
            for (int i = 0; i < 4; i++) acc[mt][nt][i] = 0.f;

    issue(0, 0);
    issue(1, 1);

    for (int kc = 0; kc < 32; kc++) {
        if (kc < 31) cp_wait<1>(); else cp_wait<0>();
        __syncthreads();

        const int stg = kc & 1;
        const uint32_t aHB = smB + stg * STG_B;
        const uint32_t aLB = aHB + SA_B;
        const uint32_t bHB = aLB + SA_B;
        const uint32_t bLB = bHB + SB_B;

#pragma unroll
        for (int s = 0; s < 2; s++) {
            const uint32_t sB = (uint32_t)(s * 32) + lmOff;

            // B fragments for this warp's 32 columns (loaded once, reused 4x)
            uint32_t bh[4][2], bl[4][2];
#pragma unroll
            for (int ntp = 0; ntp < 2; ntp++) {
                uint32_t ro = (uint32_t)((wc * 32 + ntp * 16) * 80);
                uint32_t b4[4];
                ldsm_x4(b4, bHB + ro + sB);
                bh[2 * ntp][0] = b4[0];     bh[2 * ntp][1] = b4[2];
                bh[2 * ntp + 1][0] = b4[1]; bh[2 * ntp + 1][1] = b4[3];
                ldsm_x4(b4, bLB + ro + sB);
                bl[2 * ntp][0] = b4[0];     bl[2 * ntp][1] = b4[2];
                bl[2 * ntp + 1][0] = b4[1]; bl[2 * ntp + 1][1] = b4[3];
            }
#pragma unroll
            for (int mt = 0; mt < 4; mt++) {
                uint32_t ah[4], al[4];
                uint32_t ro = (uint32_t)((wr * 64 + mt * 16) * 80);
                ldsm_x4(ah, aHB + ro + sB);
                ldsm_x4(al, aLB + ro + sB);
#pragma unroll
                for (int nt = 0; nt < 4; nt++) {
                    mma16816(acc[mt][nt], al, bh[nt]);
                    mma16816(acc[mt][nt], ah, bl[nt]);
                    mma16816(acc[mt][nt], ah, bh[nt]);
                }
            }
        }
        __syncthreads();
        if (kc + 2 < 32) issue(kc + 2, stg);
    }

    // ------------------------------- epilogue -------------------------------
#pragma unroll
    for (int mt = 0; mt < 4; mt++) {
#pragma unroll
        for (int rh = 0; rh < 2; rh++) {
            int m  = m0 + wr * 64 + mt * 16 + g + rh * 8;
            int bb = m >> 11;
            int ss = m & (SEQ - 1);
#pragma unroll
            for (int nt = 0; nt < 4; nt++) {
                float c0 = acc[mt][nt][rh * 2 + 0];
                float c1 = acc[mt][nt][rh * 2 + 1];
                int n = n0 + wc * 32 + nt * 8 + t * 2;
                if (mode == 3) {
                    *(float2*)&out[(size_t)m * DMOD + n] = make_float2(c0, c1);
                } else {
                    int h = n >> 6, i0 = n & 63;
                    size_t idx = (((size_t)(bb * NH + h)) * SEQ + ss) * DK + i0;
                    uint32_t hi, lo;
                    if (mode == 2) {
                        split2(c0, c1, hi, lo);
                        *(uint32_t*)&g_Vh[idx] = hi;
                        *(uint32_t*)&g_Vl[idx] = lo;
                    } else {
                        float2 cssn = g_cs[ss][i0 >> 1];
                        float r0 = c0 * cssn.x - c1 * cssn.y;
                        float r1 = c1 * cssn.x + c0 * cssn.y;
                        split2(r0, r1, hi, lo);
                        if (mode == 0) {
                            *(uint32_t*)&g_Qh[idx] = hi;
                            *(uint32_t*)&g_Ql[idx] = lo;
                        } else {
                            *(uint32_t*)&g_Kh[idx] = hi;
                            *(uint32_t*)&g_Kl[idx] = lo;
                        }
                    }
                }
            }
        }
    }
}

// ---------------------------------------------------------------------------
// MMA flash attention (3xBF16 split), causal.  PRE-SPLIT Q/K/V inputs,
// cp.async double-buffered, ldmatrix.x4, 3 CTAs/SM.  (R16 winning version.)
// ---------------------------------------------------------------------------
#define TPITCH  144                    // bytes per smem row (72 bf16)
#define TILE_B  (64*TPITCH)            // 9216 B per tile
#define STAGE_B (4*TILE_B)             // 36864 B per stage (Kh|Kl|Vh|Vl)
#define ASM_TOT (2*STAGE_B)            // 73728 B

__global__ __launch_bounds__(128, 3) void attn_mma_kernel()
{
    extern __shared__ char smem[];
    const uint32_t smemB = (uint32_t)__cvta_generic_to_shared(smem);

    const int tid  = threadIdx.x;
    const int w    = tid >> 5;
    const int lane = tid & 31;
    const int g = lane >> 2, t = lane & 3;
    const int qt = (int)gridDim.x - 1 - (int)blockIdx.x;   // heavy blocks first
    const int bh = blockIdx.y;
    const int q0 = qt * 64;

    const size_t hb = (size_t)bh * SEQ * DK;
    const __nv_bfloat16* kv_src[4] = {g_Kh + hb, g_Kl + hb, g_Vh + hb, g_Vl + hb};

    uint32_t qh[4][4], ql[4][4];
    {
        const __nv_bfloat16* qh0 = g_Qh + hb + (size_t)(q0 + w * 16 + g) * DK;
        const __nv_bfloat16* ql0 = g_Ql + hb + (size_t)(q0 + w * 16 + g) * DK;
#pragma unroll
        for (int ks = 0; ks < 4; ks++) {
            int c = ks * 16 + 2 * t;
            qh[ks][0] = *(const uint32_t*)&qh0[c];
            qh[ks][1] = *(const uint32_t*)&qh0[8 * DK + c];
            qh[ks][2] = *(const uint32_t*)&qh0[c + 8];
            qh[ks][3] = *(const uint32_t*)&qh0[8 * DK + c + 8];
            ql[ks][0] = *(const uint32_t*)&ql0[c];
            ql[ks][1] = *(const uint32_t*)&ql0[8 * DK + c];
            ql[ks][2] = *(const uint32_t*)&ql0[c + 8];
            ql[ks][3] = *(const uint32_t*)&ql0[8 * DK + c + 8];
        }
    }

    const uint32_t kPart = (uint32_t)((lane & 7) * TPITCH + (lane >> 3) * 16);
    const uint32_t vPart = (uint32_t)(((lane & 7) + 8 * ((lane >> 3) & 1)) * TPITCH
                                      + (lane >> 4) * 16);

    auto issue = [&](int kt, int stg) {
        uint32_t base = smemB + stg * STAGE_B;
#pragma unroll
        for (int a = 0; a < 4; a++) {
            const __nv_bfloat16* s = kv_src[a] + (size_t)kt * 64 * DK;
#pragma unroll
            for (int i = 0; i < 4; i++) {
                int c = tid + i * 128;
                cpa16(base + a * TILE_B + (c >> 3) * TPITCH + (c & 7) * 16,
                      s + (size_t)(c >> 3) * DK + (c & 7) * 8);
            }
        }
        asm volatile("cp.async.commit_group;\n" ::);
    };

    float oacc[8][4];
#pragma unroll
    for (int nt = 0; nt < 8; nt++)
#pragma unroll
        for (int i = 0; i < 4; i++) oacc[nt][i] = 0.f;
    float mrow[2] = {-1e30f, -1e30f};
    float lrow[2] = {0.f, 0.f};

    issue(0, 0);

    for (int kt = 0; kt <= qt; kt++) {
        const int stg = kt & 1;
        if (kt < qt) { issue(kt + 1, stg ^ 1); cp_wait<1>(); }
        else         { cp_wait<0>(); }
        __syncthreads();

        const uint32_t khB = smemB + stg * STAGE_B;
        const uint32_t klB = khB + TILE_B;
        const uint32_t vhB = khB + 2 * TILE_B;
        const uint32_t vlB = khB + 3 * TILE_B;

        float sacc[8][4];
#pragma unroll
        for (int nt = 0; nt < 8; nt++) {
#pragma unroll
            for (int i = 0; i < 4; i++) sacc[nt][i] = 0.f;
#pragma unroll
            for (int ks2 = 0; ks2 < 2; ks2++) {
                uint32_t bh4[4], bl4[4];
                uint32_t off = (uint32_t)(nt * 8 * TPITCH + ks2 * 64) + kPart;
                ldsm_x4(bh4, khB + off);
                ldsm_x4(bl4, klB + off);
                mma16816(sacc[nt], ql[2 * ks2],     bh4 + 0);
                mma16816(sacc[nt], qh[2 * ks2],     bl4 + 0);
                mma16816(sacc[nt], qh[2 * ks2],     bh4 + 0);
                mma16816(sacc[nt], ql[2 * ks2 + 1], bh4 + 2);
                mma16816(sacc[nt], qh[2 * ks2 + 1], bl4 + 2);
                mma16816(sacc[nt], qh[2 * ks2 + 1], bh4 + 2);
            }
        }

#pragma unroll
        for (int nt = 0; nt < 8; nt++)
#pragma unroll
            for (int i = 0; i < 4; i++) sacc[nt][i] *= 0.125f;
        if (kt == qt) {
#pragma unroll
            for (int nt = 0; nt < 8; nt++)
#pragma unroll
                for (int i = 0; i < 4; i++) {
                    int col = nt * 8 + 2 * t + (i & 1);
                    int row = w * 16 + g + 8 * (i >> 1);
                    if (col > row) sacc[nt][i] = -1e30f;
                }
        }

#pragma unroll
        for (int r = 0; r < 2; r++) {
            float mx = -1e30f;
#pragma unroll
            for (int nt = 0; nt < 8; nt++) {
                mx = fmaxf(mx, sacc[nt][2 * r]);
                mx = fmaxf(mx, sacc[nt][2 * r + 1]);
            }
            mx = fmaxf(mx, __shfl_xor_sync(0xffffffffu, mx, 1));
            mx = fmaxf(mx, __shfl_xor_sync(0xffffffffu, mx, 2));
            float mnew = fmaxf(mrow[r], mx);
            float corr = __expf(mrow[r] - mnew);
            mrow[r] = mnew;
            float rs = 0.f;
#pragma unroll
            for (int nt = 0; nt < 8; nt++) {
                float p0 = __expf(sacc[nt][2 * r]     - mnew);
                float p1 = __expf(sacc[nt][2 * r + 1] - mnew);
                sacc[nt][2 * r] = p0; sacc[nt][2 * r + 1] = p1;
                rs += p0 + p1;
            }
            rs += __shfl_xor_sync(0xffffffffu, rs, 1);
            rs += __shfl_xor_sync(0xffffffffu, rs, 2);
            lrow[r] = lrow[r] * corr + rs;
#pragma unroll
            for (int nt = 0; nt < 8; nt++) {
                oacc[nt][2 * r]     *= corr;
                oacc[nt][2 * r + 1] *= corr;
            }
        }

#pragma unroll
        for (int kc = 0; kc < 4; kc++) {
            uint32_t pah[4], pal[4];
            split2(sacc[2 * kc][0],     sacc[2 * kc][1],     pah[0], pal[0]);
            split2(sacc[2 * kc][2],     sacc[2 * kc][3],     pah[1], pal[1]);
            split2(sacc[2 * kc + 1][0], sacc[2 * kc + 1][1], pah[2], pal[2]);
            split2(sacc[2 * kc + 1][2], sacc[2 * kc + 1][3], pah[3], pal[3]);
#pragma unroll
            for (int nt2 = 0; nt2 < 4; nt2++) {
                uint32_t vh4[4], vl4[4];
                uint32_t off = (uint32_t)(kc * 16 * TPITCH + nt2 * 32) + vPart;
                ldsm_x4_t(vh4, vhB + off);
                ldsm_x4_t(vl4, vlB + off);
                mma16816(oacc[2 * nt2],     pah, vh4 + 0);
                mma16816(oacc[2 * nt2],     pah, vl4 + 0);
                mma16816(oacc[2 * nt2],     pal, vh4 + 0);
                mma16816(oacc[2 * nt2 + 1], pah, vh4 + 2);
                mma16816(oacc[2 * nt2 + 1], pah, vl4 + 2);
                mma16816(oacc[2 * nt2 + 1], pal, vh4 + 2);
            }
        }
        __syncthreads();
    }

    // epilogue: write SPLIT O (bf16 hi/lo) for the pre-split Wo GEMM
    const int bb = bh >> 4;
    const int h  = bh & 15;
#pragma unroll
    for (int r = 0; r < 2; r++) {
        float inv = 1.f / lrow[r];
        int q = q0 + w * 16 + g + 8 * r;
        size_t rowoff = ((size_t)(bb * SEQ + q)) * DMOD + h * DK;
#pragma unroll
        for (int nt = 0; nt < 8; nt++) {
            uint32_t hi, lo;
            split2(oacc[nt][2 * r] * inv, oacc[nt][2 * r + 1] * inv, hi, lo);
            *(uint32_t*)&g_Oh[rowoff + nt * 8 + 2 * t] = hi;
            *(uint32_t*)&g_Ol[rowoff + nt * 8 + 2 * t] = lo;
        }
    }
}

// ---------------------------------------------------------------------------
extern "C" void kernel_launch(void* const* d_in, const int* in_sizes, int n_in,
                              void* d_out, int out_size)
{
    const float* X  = (const float*)d_in[0];
    const float* Wq = (const float*)d_in[1];
    const float* Wk = (const float*)d_in[2];
    const float* Wv = (const float*)d_in[3];
    const float* Wo = (const float*)d_in[4];
    float* out = (float*)d_out;

    prep_kernel<<<8448, 256>>>(X, Wq, Wk, Wv, Wo);

    cudaFuncSetAttribute(gemm_mma_kernel,
                         cudaFuncAttributeMaxDynamicSharedMemorySize, GSM_TOT);
    cudaFuncSetAttribute(attn_mma_kernel,
                         cudaFuncAttributeMaxDynamicSharedMemorySize, ASM_TOT);

    // fused QKV: grid.x = 3 modes * 8 n-tiles (BN=128)
    gemm_mma_kernel<<<dim3(24, MROWS / 128), 256, GSM_TOT>>>(nullptr, -1);

    attn_mma_kernel<<<dim3(SEQ / 64, BATCH * NH), 128, ASM_TOT>>>();

    gemm_mma_kernel<<<dim3(8, MROWS / 128), 256, GSM_TOT>>>(out, 3);
}